// round 14
// baseline (speedup 1.0000x reference)
#include <cuda_runtime.h>
#include <cuda_fp16.h>
#include <math.h>
#include <stdint.h>

#define NN 32768
#define EE 524288
#define HH 128
#define BB 2048
#define LL 7
#define NF 10

// ---------------------------------------------------------------------------
// device scratch
// ---------------------------------------------------------------------------
__device__ int    g_is64;
__device__ __half g_xh[NN * HH];
__device__ __half g_xh2[NN * HH];
__device__ __half g_pd[NN * HH];       // x @ W1_top + b1 (indexed by dst)
__device__ __half g_ps[NN * HH];       // x @ W1_bot      (indexed by src)
__device__ __half g_aggh[NN * HH];     // per-node aggregated H (fp16)
__device__ int    g_degi[NN];
__device__ float  g_head[NN * 30];
__device__ int    g_srcA[EE];
__device__ int    g_dstA[EE];
__device__ int    g_csrs[EE];          // src per CSR slot (grouped by dst)
__device__ int    g_rowp[NN + 1];
__device__ int    g_cursor[NN];
__device__ float  g_mfw[LL * 16384];   // Mf = mW2 @ uW1_bot (fp32, k-major)
__device__ float  g_vb[LL * 128];      // v  = mb2 @ uW1_bot
// fragment-order fp16 weight images (uint4 = one lane's 16B B-fragment)
__device__ uint4 g_mW1f[LL * 4096];
__device__ uint4 g_Mff[LL * 2048];
__device__ uint4 g_uW1f[LL * 4096];
__device__ uint4 g_uW2f[LL * 2048];
__device__ uint4 g_eW1f[1024];         // K=64 (4 ks)
__device__ uint4 g_eW2f[2048];         // K=128 (8 ks)
__device__ uint4 g_hW1f[2048];         // head W1, K=128
__device__ uint4 g_hW2f[2048];         // head W2, K=128, N=30 (padded)

// pitches in halfs
#define PB 136   // K=128 + 8 pad  (272 B)
#define PE 72    // K=64  + 8 pad

// ---- upd kernel smem: three PB tiles (x | agg | H) + ctrl ----
#define SX_OFF   0
#define SG_OFF   (128 * PB * 2)                  // 34816
#define SH_OFF   (2 * 128 * PB * 2)              // 69632
#define SB1_OFF  (3 * 128 * PB * 2)              // 104448
#define SB2_OFF  (SB1_OFF + 512)
#define SB3_OFF  (SB2_OFF + 512)                 // v vector
#define SDG_OFF  (SB3_OFF + 512)                 // deg[128]
#define DYNB_U   (SDG_OFF + 512)

// ---- embed smem ----
#define EA_OFF   0
#define EH_OFF   (128 * PE * 2)                  // 18432
#define EB1_OFF  (EH_OFF + 128 * PB * 2)         // 53248
#define EB2_OFF  (EB1_OFF + 512)
#define DYNB_EM  (EB2_OFF + 512)

// ---- head smem ----
#define HA_OFF   0
#define HHS_OFF  (128 * PB * 2)
#define HB1_OFF  (HHS_OFF + 128 * PB * 2)
#define HB2_OFF  (HB1_OFF + 512)
#define DYNB_H   (HB2_OFF + 512)

__device__ __forceinline__ uint32_t smem_u32(const void* p) {
    uint32_t a;
    asm("{ .reg .u64 t; cvta.to.shared.u64 t, %1; cvt.u32.u64 %0, t; }" : "=r"(a) : "l"(p));
    return a;
}

__device__ __forceinline__ void ldsm_x4(uint32_t r[4], uint32_t addr) {
    asm volatile("ldmatrix.sync.aligned.m8n8.x4.shared.b16 {%0,%1,%2,%3}, [%4];"
                 : "=r"(r[0]), "=r"(r[1]), "=r"(r[2]), "=r"(r[3]) : "r"(addr));
}

__device__ __forceinline__ void mma16816(float c[4], const uint32_t a[4],
                                         uint32_t b0, uint32_t b1) {
    asm volatile(
        "mma.sync.aligned.m16n8k16.row.col.f32.f16.f16.f32 "
        "{%0,%1,%2,%3},{%4,%5,%6,%7},{%8,%9},{%0,%1,%2,%3};"
        : "+f"(c[0]), "+f"(c[1]), "+f"(c[2]), "+f"(c[3])
        : "r"(a[0]), "r"(a[1]), "r"(a[2]), "r"(a[3]), "r"(b0), "r"(b1));
}

__device__ __forceinline__ int load_idx(const void* p, long long i) {
    if (g_is64) return (int)((const long long*)p)[i];
    return ((const int*)p)[i];
}

__global__ void detect_kernel(const int* e) {
    if (threadIdx.x == 0) {
        int is64 = 1;
        for (int i = 1; i < 256; i += 2)
            if (e[i] != 0) { is64 = 0; break; }
        g_is64 = is64;
    }
}

__global__ void idx_kernel(const void* __restrict__ eidx) {
    int i = blockIdx.x * blockDim.x + threadIdx.x;
    if (i >= EE) return;
    g_srcA[i] = load_idx(eidx, i);
    int d = load_idx(eidx, (long long)EE + i);
    g_dstA[i] = d;
    atomicAdd(&g_degi[d], 1);
}

__global__ void scan_kernel() {
    __shared__ int s[1024];
    __shared__ int srun;
    int tid = threadIdx.x;
    if (tid == 0) srun = 0;
    __syncthreads();
    for (int c = 0; c < NN; c += 1024) {
        int v = g_degi[c + tid];
        s[tid] = v;
        __syncthreads();
        for (int off = 1; off < 1024; off <<= 1) {
            int t = (tid >= off) ? s[tid - off] : 0;
            __syncthreads();
            s[tid] += t;
            __syncthreads();
        }
        int excl = srun + s[tid] - v;
        g_rowp[c + tid] = excl;
        g_cursor[c + tid] = excl;
        __syncthreads();
        if (tid == 0) srun += s[1023];
        __syncthreads();
    }
    if (tid == 0) g_rowp[NN] = srun;
}

__global__ void fill_kernel() {
    int i = blockIdx.x * blockDim.x + threadIdx.x;
    if (i >= EE) return;
    int pos = atomicAdd(&g_cursor[g_dstA[i]], 1);
    g_csrs[pos] = g_srcA[i];
}

// ---------------------------------------------------------------------------
// Mf = mW2 @ uW1_bot (per layer, fp32), v = mb2 @ uW1_bot
// ---------------------------------------------------------------------------
__global__ void mf_kernel(const float* __restrict__ msgW2, const float* __restrict__ updW1,
                          const float* __restrict__ msgb2) {
    __shared__ float As[128 * 33];
    __shared__ float Bs[32 * 128];
    int l = blockIdx.x;
    const float* A = msgW2 + (size_t)l * 128 * 128;
    const float* B = updW1 + (size_t)l * 256 * 128 + 128 * 128;  // bottom half
    float* C = g_mfw + (size_t)l * 16384;
    int tid = threadIdx.x, tx = tid & 15, ty = tid >> 4;
    float acc[8][8];
#pragma unroll
    for (int i = 0; i < 8; i++)
#pragma unroll
        for (int j = 0; j < 8; j++) acc[i][j] = 0.f;

    for (int kc = 0; kc < 128; kc += 32) {
        for (int t = tid; t < 128 * 32; t += 256) {
            int r = t >> 5, c = t & 31;
            As[r * 33 + c] = A[r * 128 + kc + c];
        }
        for (int t = tid; t < 32 * 128; t += 256) {
            int r = t >> 7, c = t & 127;
            Bs[t] = B[(kc + r) * 128 + c];
        }
        __syncthreads();
#pragma unroll
        for (int k = 0; k < 32; k++) {
            float a[8], b[8];
#pragma unroll
            for (int i = 0; i < 8; i++) a[i] = As[(ty * 8 + i) * 33 + k];
#pragma unroll
            for (int j = 0; j < 8; j++) b[j] = Bs[k * 128 + tx * 8 + j];
#pragma unroll
            for (int i = 0; i < 8; i++)
#pragma unroll
                for (int j = 0; j < 8; j++) acc[i][j] += a[i] * b[j];
        }
        __syncthreads();
    }
#pragma unroll
    for (int i = 0; i < 8; i++)
#pragma unroll
        for (int j = 0; j < 8; j++)
            C[(ty * 8 + i) * 128 + tx * 8 + j] = acc[i][j];

    if (tid < 128) {
        float s = 0.f;
        for (int j = 0; j < 128; j++)
            s += msgb2[l * 128 + j] * B[j * 128 + tid];
        g_vb[l * 128 + tid] = s;
    }
}

// ---------------------------------------------------------------------------
// weight prep: fp32 [k][n] -> fragment-order fp16 image
// ---------------------------------------------------------------------------
__global__ void prep_fragk(const float* __restrict__ src, __half* __restrict__ dst,
                           int Ktrue, int Ntrue, int srcWidth,
                           int srcStride, int dstStride) {
    int l = blockIdx.x, ks = blockIdx.y;
    src += (size_t)l * srcStride;
    dst += (size_t)l * dstStride + (size_t)ks * 2048;
    int tid = threadIdx.x;
    int lane = tid & 31, p = (tid >> 5) & 3, wn = (tid >> 7) & 1;
    uint4 v;
    __half* hv = (__half*)&v;
#pragma unroll
    for (int h = 0; h < 8; h++) {
        int k = ks * 16 + (lane & 3) * 2 + (h & 1) + ((h >> 1) & 1) * 8;
        int n = wn * 64 + p * 16 + (lane >> 2) + (h >> 2) * 8;
        hv[h] = (k < Ktrue && n < Ntrue) ? __float2half(src[k * srcWidth + n]) : __half(0.f);
    }
    ((uint4*)dst)[tid] = v;
}

// ---------------------------------------------------------------------------
// HMMA core
// ---------------------------------------------------------------------------
struct MlpCtx {
    uint32_t sb;
    int lane, wm, wn;
    float acc[2][8][4];
};

__device__ __forceinline__ void gemm_zero(MlpCtx& c) {
#pragma unroll
    for (int mt = 0; mt < 2; mt++)
#pragma unroll
        for (int nt = 0; nt < 8; nt++)
#pragma unroll
            for (int q = 0; q < 4; q++) c.acc[mt][nt][q] = 0.f;
}

__device__ __forceinline__ void gemm_run(MlpCtx& c, uint32_t aoff, uint32_t pbytes,
                                         const uint4* __restrict__ wf, int ksteps) {
    int l = c.lane;
    uint32_t aBase = c.sb + aoff +
        (uint32_t)(c.wm * 32 + (l & 7) + ((l >> 3) & 1) * 8) * pbytes + (l >> 4) * 16;
    const uint4* wb = wf + c.wn * 128 + l;
#pragma unroll
    for (int ks = 0; ks < 16; ks++) {
        if (ks >= ksteps) break;
        uint32_t a0[4], a1[4];
        uint4 q[4];
#pragma unroll
        for (int p = 0; p < 4; p++) q[p] = __ldg(wb + ks * 256 + p * 32);
        ldsm_x4(a0, aBase + ks * 32);
        ldsm_x4(a1, aBase + 16 * pbytes + ks * 32);
#pragma unroll
        for (int p = 0; p < 4; p++) {
            mma16816(c.acc[0][2 * p],     a0, q[p].x, q[p].y);
            mma16816(c.acc[0][2 * p + 1], a0, q[p].z, q[p].w);
            mma16816(c.acc[1][2 * p],     a1, q[p].x, q[p].y);
            mma16816(c.acc[1][2 * p + 1], a1, q[p].z, q[p].w);
        }
    }
}

__device__ __forceinline__ void epi_relu_h(MlpCtx& c, char* sm, int shOff, int b1Off) {
    int g = c.lane >> 2, t = c.lane & 3;
    const float* sb1 = (const float*)(sm + b1Off);
#pragma unroll
    for (int mt = 0; mt < 2; mt++)
#pragma unroll
        for (int nt = 0; nt < 8; nt++) {
            int row = c.wm * 32 + mt * 16 + g;
            int col = c.wn * 64 + nt * 8 + t * 2;
            float v0 = c.acc[mt][nt][0] + sb1[col];
            float v1 = c.acc[mt][nt][1] + sb1[col + 1];
            float v2 = c.acc[mt][nt][2] + sb1[col];
            float v3 = c.acc[mt][nt][3] + sb1[col + 1];
            v0 = v0 > 0.f ? v0 : 0.f; v1 = v1 > 0.f ? v1 : 0.f;
            v2 = v2 > 0.f ? v2 : 0.f; v3 = v3 > 0.f ? v3 : 0.f;
            *(__half2*)(sm + shOff + row * (PB * 2) + col * 2) = __floats2half2_rn(v0, v1);
            *(__half2*)(sm + shOff + (row + 8) * (PB * 2) + col * 2) = __floats2half2_rn(v2, v3);
        }
}

// hidden epilogue with per-row deg*v bias: relu(acc + b1[col] + deg[row]*v[col])
__device__ __forceinline__ void epi_relu_hv(MlpCtx& c, char* sm) {
    int g = c.lane >> 2, t = c.lane & 3;
    const float* sb1 = (const float*)(sm + SB1_OFF);
    const float* sv  = (const float*)(sm + SB3_OFF);
    const float* sdg = (const float*)(sm + SDG_OFF);
#pragma unroll
    for (int mt = 0; mt < 2; mt++)
#pragma unroll
        for (int nt = 0; nt < 8; nt++) {
            int row = c.wm * 32 + mt * 16 + g;
            int col = c.wn * 64 + nt * 8 + t * 2;
            float d0 = sdg[row], d1 = sdg[row + 8];
            float v0 = c.acc[mt][nt][0] + sb1[col]     + d0 * sv[col];
            float v1 = c.acc[mt][nt][1] + sb1[col + 1] + d0 * sv[col + 1];
            float v2 = c.acc[mt][nt][2] + sb1[col]     + d1 * sv[col];
            float v3 = c.acc[mt][nt][3] + sb1[col + 1] + d1 * sv[col + 1];
            v0 = v0 > 0.f ? v0 : 0.f; v1 = v1 > 0.f ? v1 : 0.f;
            v2 = v2 > 0.f ? v2 : 0.f; v3 = v3 > 0.f ? v3 : 0.f;
            *(__half2*)(sm + SH_OFF + row * (PB * 2) + col * 2) = __floats2half2_rn(v0, v1);
            *(__half2*)(sm + SH_OFF + (row + 8) * (PB * 2) + col * 2) = __floats2half2_rn(v2, v3);
        }
}

__device__ __forceinline__ void epi_write_x_stage(MlpCtx& c, char* sm, int b2Off,
                                                  __half* __restrict__ xout, int n0,
                                                  int stageOff, bool doStage) {
    int g = c.lane >> 2, t = c.lane & 3;
    const float* sb2 = (const float*)(sm + b2Off);
#pragma unroll
    for (int mt = 0; mt < 2; mt++)
#pragma unroll
        for (int nt = 0; nt < 8; nt++) {
            int row = c.wm * 32 + mt * 16 + g;
            int col = c.wn * 64 + nt * 8 + t * 2;
            float bb0 = sb2[col], bb1 = sb2[col + 1];
            __half2 h0 = __floats2half2_rn(c.acc[mt][nt][0] + bb0, c.acc[mt][nt][1] + bb1);
            __half2 h1 = __floats2half2_rn(c.acc[mt][nt][2] + bb0, c.acc[mt][nt][3] + bb1);
            *(__half2*)(xout + (size_t)(n0 + row) * HH + col) = h0;
            *(__half2*)(xout + (size_t)(n0 + row + 8) * HH + col) = h1;
            if (doStage) {
                *(__half2*)(sm + stageOff + row * (PB * 2) + col * 2) = h0;
                *(__half2*)(sm + stageOff + (row + 8) * (PB * 2) + col * 2) = h1;
            }
        }
}

__device__ __forceinline__ void epi_write_gb(MlpCtx& c, __half* __restrict__ pout, int n0,
                                             const float* __restrict__ bias) {
    int g = c.lane >> 2, t = c.lane & 3;
#pragma unroll
    for (int mt = 0; mt < 2; mt++)
#pragma unroll
        for (int nt = 0; nt < 8; nt++) {
            int row = c.wm * 32 + mt * 16 + g;
            int col = c.wn * 64 + nt * 8 + t * 2;
            float bb0 = 0.f, bb1 = 0.f;
            if (bias) { bb0 = __ldg(bias + col); bb1 = __ldg(bias + col + 1); }
            __half2 h0 = __floats2half2_rn(c.acc[mt][nt][0] + bb0, c.acc[mt][nt][1] + bb1);
            __half2 h1 = __floats2half2_rn(c.acc[mt][nt][2] + bb0, c.acc[mt][nt][3] + bb1);
            *(__half2*)(pout + (size_t)(n0 + row) * HH + col) = h0;
            *(__half2*)(pout + (size_t)(n0 + row + 8) * HH + col) = h1;
        }
}

__device__ __forceinline__ void pre_from_stage(MlpCtx& c, uint32_t aoff,
                                               const uint4* __restrict__ nW1f,
                                               const float* __restrict__ nb1,
                                               __half* __restrict__ pd,
                                               __half* __restrict__ ps, int n0) {
    gemm_zero(c);
    gemm_run(c, aoff, PB * 2, nW1f, 8);
    epi_write_gb(c, pd, n0, nb1);
    gemm_zero(c);
    gemm_run(c, aoff, PB * 2, nW1f + 2048, 8);
    epi_write_gb(c, ps, n0, (const float*)0);
}

// ---------------------------------------------------------------------------
// CSR aggregation: one warp per node, two edges in flight (half-warp each)
// lane = half*16 + li ; li owns 16B (8 halfs) of the 256B row
// ---------------------------------------------------------------------------
__global__ void __launch_bounds__(256)
agg_csr(const __half* __restrict__ pd, const __half* __restrict__ ps,
        const int* __restrict__ csrs, const int* __restrict__ rowp,
        __half* __restrict__ aggH) {
    int w = (blockIdx.x * 256 + threadIdx.x) >> 5;
    int lane = threadIdx.x & 31;
    int half = lane >> 4, li = lane & 15;

    int beg = __ldg(rowp + w), end = __ldg(rowp + w + 1);
    uint4 pdu = __ldg((const uint4*)(pd + (size_t)w * HH) + li);
    float p[8], a[8];
    {
        const __half2* ph = (const __half2*)&pdu;
#pragma unroll
        for (int q = 0; q < 4; q++) {
            float2 f = __half22float2(ph[q]);
            p[2 * q] = f.x; p[2 * q + 1] = f.y;
        }
    }
#pragma unroll
    for (int j = 0; j < 8; j++) a[j] = 0.f;

#pragma unroll 2
    for (int i = beg + half; i < end; i += 2) {
        int s = __ldg(csrs + i);
        uint4 v = __ldg((const uint4*)(ps + (size_t)s * HH) + li);
        const __half2* vh = (const __half2*)&v;
#pragma unroll
        for (int q = 0; q < 4; q++) {
            float2 f = __half22float2(vh[q]);
            a[2 * q]     += fmaxf(p[2 * q] + f.x, 0.f);
            a[2 * q + 1] += fmaxf(p[2 * q + 1] + f.y, 0.f);
        }
    }
#pragma unroll
    for (int j = 0; j < 8; j++)
        a[j] += __shfl_xor_sync(0xffffffffu, a[j], 16);

    if (half == 0) {
        uint4 ov;
        __half2* oh = (__half2*)&ov;
#pragma unroll
        for (int q = 0; q < 4; q++)
            oh[q] = __floats2half2_rn(a[2 * q], a[2 * q + 1]);
        ((uint4*)(aggH + (size_t)w * HH))[li] = ov;
    }
}

// ---------------------------------------------------------------------------
// upd kernel: hidden = relu(x@uW1t + aggH@Mf + ub1 + deg*v); x2 = hidden@uW2+ub2
// fused next-layer pre
// ---------------------------------------------------------------------------
__global__ void __launch_bounds__(256, 2)
upd_tc(const __half* __restrict__ xh, const __half* __restrict__ aggH,
       const uint4* __restrict__ Mff, const float* __restrict__ vb,
       const int* __restrict__ degi,
       const uint4* __restrict__ wf1, const uint4* __restrict__ wf2,
       const float* __restrict__ b1, const float* __restrict__ b2,
       __half* __restrict__ xout,
       const uint4* __restrict__ nW1f, const float* __restrict__ nb1,
       __half* __restrict__ pd, __half* __restrict__ ps, int do_pre) {
    extern __shared__ __align__(128) char sm[];
    MlpCtx c;
    c.sb = smem_u32(sm);
    int tid = threadIdx.x;
    c.lane = tid & 31;
    int warp = tid >> 5;
    c.wm = warp >> 1; c.wn = warp & 1;
    int n0 = blockIdx.x * 128;

    if (tid < 128) {
        ((float*)(sm + SB1_OFF))[tid] = b1[tid];
        ((float*)(sm + SB2_OFF))[tid] = b2[tid];
        ((float*)(sm + SB3_OFF))[tid] = vb[tid];
        ((float*)(sm + SDG_OFF))[tid] = (float)degi[n0 + tid];
    }
    // gather: h=0 -> x row into SX; h=1 -> aggH row into SG (both PB pitch)
    {
        int r = tid >> 1, h = tid & 1;
        int node = n0 + r;
        const uint4* row = (const uint4*)((h ? aggH : xh) + (size_t)node * HH);
        uint4* dstp = (uint4*)(sm + (h ? SG_OFF : SX_OFF) + r * (PB * 2));
#pragma unroll
        for (int j = 0; j < 16; j++) dstp[j] = __ldg(row + j);
    }
    __syncthreads();

    // hidden = x@uW1_top + aggH@Mf (accumulated), + bias in epilogue
    gemm_zero(c);
    gemm_run(c, SX_OFF, PB * 2, wf1, 8);
    gemm_run(c, SG_OFF, PB * 2, Mff, 8);
    epi_relu_hv(c, sm);
    __syncthreads();

    gemm_zero(c);
    gemm_run(c, SH_OFF, PB * 2, wf2, 8);
    epi_write_x_stage(c, sm, SB2_OFF, xout, n0, SX_OFF, do_pre != 0);

    if (do_pre) {
        __syncthreads();
        pre_from_stage(c, SX_OFF, nW1f, nb1, pd, ps, n0);
    }
}

// ---------------------------------------------------------------------------
// embed via HMMA + fused layer-0 pre
// ---------------------------------------------------------------------------
__global__ void __launch_bounds__(256, 2)
embed_tc(const float* __restrict__ loc, const float* __restrict__ vel,
         const uint4* __restrict__ wf1, const uint4* __restrict__ wf2,
         const float* __restrict__ b1, const float* __restrict__ b2,
         __half* __restrict__ xout,
         const uint4* __restrict__ nW1f, const float* __restrict__ nb1,
         __half* __restrict__ pd, __half* __restrict__ ps) {
    extern __shared__ __align__(128) char sm[];
    MlpCtx c;
    c.sb = smem_u32(sm);
    int tid = threadIdx.x;
    c.lane = tid & 31;
    int warp = tid >> 5;
    c.wm = warp >> 1; c.wn = warp & 1;
    int n0 = blockIdx.x * 128;

    if (tid < 128) {
        ((float*)(sm + EB1_OFF))[tid] = b1[tid];
        ((float*)(sm + EB2_OFF))[tid] = b2[tid];
    }
    if (tid < 128) {
        int r = tid;
        const float* lrow = loc + (size_t)(n0 + r) * 30;
        const float* vrow = vel + (size_t)(n0 + r) * 30;
        __half* drow = (__half*)(sm + EA_OFF + r * (PE * 2));
#pragma unroll
        for (int k = 0; k < 64; k++) {
            float v = 0.f;
            if (k < 60) {
                int f = k / 6, c6 = k % 6;
                v = (c6 < 3) ? lrow[f * 3 + c6] : vrow[f * 3 + c6 - 3];
            }
            drow[k] = __float2half(v);
        }
    }
    __syncthreads();

    gemm_zero(c);
    gemm_run(c, EA_OFF, PE * 2, wf1, 4);
    epi_relu_h(c, sm, EH_OFF, EB1_OFF);
    __syncthreads();

    gemm_zero(c);
    gemm_run(c, EH_OFF, PB * 2, wf2, 8);
    __syncthreads();
    epi_write_x_stage(c, sm, EB2_OFF, xout, n0, EH_OFF, true);
    __syncthreads();
    pre_from_stage(c, EH_OFF, nW1f, nb1, pd, ps, n0);
}

// ---------------------------------------------------------------------------
// head via HMMA
// ---------------------------------------------------------------------------
__global__ void __launch_bounds__(256, 2)
head_tc(const __half* __restrict__ xh,
        const uint4* __restrict__ wf1, const uint4* __restrict__ wf2,
        const float* __restrict__ b1, const float* __restrict__ b2,
        float* __restrict__ hout) {
    extern __shared__ __align__(128) char sm[];
    MlpCtx c;
    c.sb = smem_u32(sm);
    int tid = threadIdx.x;
    c.lane = tid & 31;
    int warp = tid >> 5;
    c.wm = warp >> 1; c.wn = warp & 1;
    int n0 = blockIdx.x * 128;

    if (tid < 128) ((float*)(sm + HB1_OFF))[tid] = b1[tid];
    if (tid < 30)  ((float*)(sm + HB2_OFF))[tid] = b2[tid];
    {
        int r = tid >> 1, h = tid & 1;
        const uint4* row = (const uint4*)xh + (size_t)(n0 + r) * 16 + h * 8;
        uint4* dstp = (uint4*)(sm + HA_OFF + r * (PB * 2)) + h * 8;
#pragma unroll
        for (int j = 0; j < 8; j++) dstp[j] = __ldg(row + j);
    }
    __syncthreads();

    gemm_zero(c);
    gemm_run(c, HA_OFF, PB * 2, wf1, 8);
    epi_relu_h(c, sm, HHS_OFF, HB1_OFF);
    __syncthreads();

    gemm_zero(c);
    gemm_run(c, HHS_OFF, PB * 2, wf2, 8);
    {
        int g = c.lane >> 2, t = c.lane & 3;
        const float* sb2 = (const float*)(sm + HB2_OFF);
        if (c.wn == 0) {
#pragma unroll
            for (int mt = 0; mt < 2; mt++)
#pragma unroll
                for (int nt = 0; nt < 4; nt++) {
                    int row = c.wm * 32 + mt * 16 + g;
                    int col = nt * 8 + t * 2;
                    if (col < 30) {
                        hout[(size_t)(n0 + row) * 30 + col] = c.acc[mt][nt][0] + sb2[col];
                        hout[(size_t)(n0 + row + 8) * 30 + col] = c.acc[mt][nt][2] + sb2[col];
                    }
                    if (col + 1 < 30) {
                        hout[(size_t)(n0 + row) * 30 + col + 1] = c.acc[mt][nt][1] + sb2[col + 1];
                        hout[(size_t)(n0 + row + 8) * 30 + col + 1] = c.acc[mt][nt][3] + sb2[col + 1];
                    }
                }
        }
    }
}

// ---------------------------------------------------------------------------
// loss
// ---------------------------------------------------------------------------
__global__ void loss_kernel(const float* __restrict__ hout, const float* __restrict__ loc,
                            const float* __restrict__ y, float* __restrict__ out) {
    int w = (blockIdx.x * blockDim.x + threadIdx.x) >> 5;
    int lane = threadIdx.x & 31;
    if (w >= BB) return;
    float ade = 0.f, fde = 0.f;
    for (int p = lane; p < 160; p += 32) {
        int node = w * 16 + p / NF;
        int f = p % NF;
        int base = node * 30 + f * 3;
        float dx = hout[base] + loc[base] - y[base];
        float dy = hout[base + 1] + loc[base + 1] - y[base + 1];
        float dz = hout[base + 2] + loc[base + 2] - y[base + 2];
        float d = sqrtf(dx * dx + dy * dy + dz * dz);
        ade += d;
        if (f == NF - 1) fde += d;
    }
#pragma unroll
    for (int o = 16; o; o >>= 1) {
        ade += __shfl_down_sync(0xffffffffu, ade, o);
        fde += __shfl_down_sync(0xffffffffu, fde, o);
    }
    if (lane == 0) {
        out[1 + w] = ade / 160.f;
        out[1 + BB + w] = fde / 16.f;
    }
}

__global__ void final_kernel(float* __restrict__ out) {
    __shared__ float s[256];
    float v = 0.f;
    for (int i = threadIdx.x; i < BB; i += 256) v += out[1 + i];
    s[threadIdx.x] = v;
    __syncthreads();
    for (int o = 128; o; o >>= 1) {
        if (threadIdx.x < o) s[threadIdx.x] += s[threadIdx.x + o];
        __syncthreads();
    }
    if (threadIdx.x == 0) out[0] = s[0] / (float)BB;
}

// ---------------------------------------------------------------------------
// host
// ---------------------------------------------------------------------------
extern "C" void kernel_launch(void* const* d_in, const int* in_sizes, int n_in,
                              void* d_out, int out_size) {
    int o = (n_in > 4 && in_sizes[4] == 1) ? 1 : 0;
    const float* loc = (const float*)d_in[0];
    const float* vel = (const float*)d_in[1];
    const float* y   = (const float*)d_in[2];
    const void*  eix = d_in[3];
    const float* embW1 = (const float*)d_in[4 + o];
    const float* embb1 = (const float*)d_in[5 + o];
    const float* embW2 = (const float*)d_in[6 + o];
    const float* embb2 = (const float*)d_in[7 + o];
    const float* msgW1 = (const float*)d_in[8 + o];
    const float* msgb1 = (const float*)d_in[9 + o];
    const float* msgW2 = (const float*)d_in[10 + o];
    const float* msgb2 = (const float*)d_in[11 + o];
    const float* updW1 = (const float*)d_in[12 + o];
    const float* updb1 = (const float*)d_in[13 + o];
    const float* updW2 = (const float*)d_in[14 + o];
    const float* updb2 = (const float*)d_in[15 + o];
    const float* hW1 = (const float*)d_in[16 + o];
    const float* hb1 = (const float*)d_in[17 + o];
    const float* hW2 = (const float*)d_in[18 + o];
    const float* hb2 = (const float*)d_in[19 + o];
    float* out = (float*)d_out;

    cudaFuncSetAttribute(upd_tc, cudaFuncAttributeMaxDynamicSharedMemorySize, DYNB_U);
    cudaFuncSetAttribute(embed_tc, cudaFuncAttributeMaxDynamicSharedMemorySize, DYNB_EM);
    cudaFuncSetAttribute(head_tc, cudaFuncAttributeMaxDynamicSharedMemorySize, DYNB_H);

    __half *xhp, *xh2p, *pdp, *psp, *agghp;
    float *headp, *mfwp, *vbp;
    int *degip, *csrsp, *rowpp;
    uint4 *mW1f, *Mff, *uW1f, *uW2f, *eW1f, *eW2f, *hW1f, *hW2f;
    cudaGetSymbolAddress((void**)&xhp, g_xh);
    cudaGetSymbolAddress((void**)&xh2p, g_xh2);
    cudaGetSymbolAddress((void**)&pdp, g_pd);
    cudaGetSymbolAddress((void**)&psp, g_ps);
    cudaGetSymbolAddress((void**)&agghp, g_aggh);
    cudaGetSymbolAddress((void**)&degip, g_degi);
    cudaGetSymbolAddress((void**)&headp, g_head);
    cudaGetSymbolAddress((void**)&csrsp, g_csrs);
    cudaGetSymbolAddress((void**)&rowpp, g_rowp);
    cudaGetSymbolAddress((void**)&mfwp, g_mfw);
    cudaGetSymbolAddress((void**)&vbp, g_vb);
    cudaGetSymbolAddress((void**)&mW1f, g_mW1f);
    cudaGetSymbolAddress((void**)&Mff, g_Mff);
    cudaGetSymbolAddress((void**)&uW1f, g_uW1f);
    cudaGetSymbolAddress((void**)&uW2f, g_uW2f);
    cudaGetSymbolAddress((void**)&eW1f, g_eW1f);
    cudaGetSymbolAddress((void**)&eW2f, g_eW2f);
    cudaGetSymbolAddress((void**)&hW1f, g_hW1f);
    cudaGetSymbolAddress((void**)&hW2f, g_hW2f);

    detect_kernel<<<1, 32>>>((const int*)eix);
    cudaMemsetAsync(degip, 0, NN * sizeof(int));
    idx_kernel<<<EE / 256, 256>>>(eix);
    scan_kernel<<<1, 1024>>>();
    fill_kernel<<<EE / 256, 256>>>();
    mf_kernel<<<LL, 256>>>(msgW2, updW1, msgb2);
    prep_fragk<<<dim3(LL, 16), 256>>>(msgW1, (__half*)mW1f, 256, 128, 128, 256 * 128, 32768);
    prep_fragk<<<dim3(LL, 16), 256>>>(updW1, (__half*)uW1f, 256, 128, 128, 256 * 128, 32768);
    prep_fragk<<<dim3(LL, 8), 256>>>(updW2, (__half*)uW2f, 128, 128, 128, 128 * 128, 16384);
    prep_fragk<<<dim3(LL, 8), 256>>>(mfwp, (__half*)Mff, 128, 128, 128, 16384, 16384);
    prep_fragk<<<dim3(1, 4), 256>>>(embW1, (__half*)eW1f, 60, 128, 128, 0, 0);
    prep_fragk<<<dim3(1, 8), 256>>>(embW2, (__half*)eW2f, 128, 128, 128, 0, 0);
    prep_fragk<<<dim3(1, 8), 256>>>(hW1, (__half*)hW1f, 128, 128, 128, 0, 0);
    prep_fragk<<<dim3(1, 8), 256>>>(hW2, (__half*)hW2f, 128, 30, 30, 0, 0);

    embed_tc<<<NN / 128, 256, DYNB_EM>>>(loc, vel, eW1f, eW2f, embb1, embb2, xhp,
                                         mW1f, msgb1, pdp, psp);

    __half* xa = xhp;
    __half* xb = xh2p;
    for (int i = 0; i < LL; i++) {
        agg_csr<<<NN / 8, 256>>>(pdp, psp, csrsp, rowpp, agghp);
        upd_tc<<<NN / 128, 256, DYNB_U>>>(
            xa, agghp,
            Mff + (size_t)i * 2048, vbp + (size_t)i * 128, degip,
            uW1f + (size_t)i * 4096, uW2f + (size_t)i * 2048,
            updb1 + (size_t)i * HH, updb2 + (size_t)i * HH, xb,
            mW1f + (size_t)(i + 1 < LL ? i + 1 : 0) * 4096,
            msgb1 + (size_t)(i + 1 < LL ? i + 1 : 0) * HH, pdp, psp,
            i + 1 < LL ? 1 : 0);
        __half* t = xa; xa = xb; xb = t;
    }
    head_tc<<<NN / 128, 256, DYNB_H>>>(xa, hW1f, hW2f, hb1, hb2, headp);
    loss_kernel<<<(BB * 32 + 127) / 128, 128>>>(headp, loc, y, out);
    final_kernel<<<1, 256>>>(out);
}

// round 16
// speedup vs baseline: 1.0303x; 1.0303x over previous
#include <cuda_runtime.h>
#include <cuda_fp16.h>
#include <math.h>
#include <stdint.h>

#define NN 32768
#define EE 524288
#define HH 128
#define BB 2048
#define LL 7
#define NF 10

// ---------------------------------------------------------------------------
// device scratch
// ---------------------------------------------------------------------------
__device__ int    g_is64;
__device__ __half g_xh[NN * HH];
__device__ __half g_xh2[NN * HH];
__device__ __half g_pd[NN * HH];       // x @ W1_top + b1 (indexed by dst)
__device__ __half g_ps[NN * HH];       // x @ W1_bot      (indexed by src)
__device__ __half g_aggh[NN * HH];     // per-node aggregated H (fp16)
__device__ int    g_degi[NN];
__device__ float  g_head[NN * 30];
__device__ int    g_srcA[EE];
__device__ int    g_dstA[EE];
__device__ int    g_csrs[EE];          // src per CSR slot (grouped by dst)
__device__ int    g_rowp[NN + 1];
__device__ int    g_cursor[NN];
__device__ float  g_mfw[LL * 16384];   // Mf = mW2 @ uW1_bot (fp32, k-major)
__device__ float  g_vb[LL * 128];      // v  = mb2 @ uW1_bot
// fragment-order fp16 weight images (uint4 = one lane's 16B B-fragment)
__device__ uint4 g_mW1f[LL * 4096];
__device__ uint4 g_Mff[LL * 2048];
__device__ uint4 g_uW1f[LL * 4096];
__device__ uint4 g_uW2f[LL * 2048];
__device__ uint4 g_eW1f[1024];         // K=64 (4 ks)
__device__ uint4 g_eW2f[2048];         // K=128 (8 ks)
__device__ uint4 g_hW1f[2048];         // head W1, K=128
__device__ uint4 g_hW2f[2048];         // head W2, K=128, N=30 (padded)

// pitches in halfs
#define PB 136   // K=128 + 8 pad  (272 B)
#define PE 72    // K=64  + 8 pad

// ---- upd kernel smem: three PB tiles (x | agg | H) + ctrl ----
#define SX_OFF   0
#define SG_OFF   (128 * PB * 2)                  // 34816
#define SH_OFF   (2 * 128 * PB * 2)              // 69632
#define SB1_OFF  (3 * 128 * PB * 2)              // 104448
#define SB2_OFF  (SB1_OFF + 512)
#define SB3_OFF  (SB2_OFF + 512)                 // v vector
#define SDG_OFF  (SB3_OFF + 512)                 // deg[128]
#define DYNB_U   (SDG_OFF + 512)

// ---- embed smem ----
#define EA_OFF   0
#define EH_OFF   (128 * PE * 2)                  // 18432
#define EB1_OFF  (EH_OFF + 128 * PB * 2)         // 53248
#define EB2_OFF  (EB1_OFF + 512)
#define DYNB_EM  (EB2_OFF + 512)

// ---- head smem ----
#define HA_OFF   0
#define HHS_OFF  (128 * PB * 2)
#define HB1_OFF  (HHS_OFF + 128 * PB * 2)
#define HB2_OFF  (HB1_OFF + 512)
#define DYNB_H   (HB2_OFF + 512)

__device__ __forceinline__ uint32_t smem_u32(const void* p) {
    uint32_t a;
    asm("{ .reg .u64 t; cvta.to.shared.u64 t, %1; cvt.u32.u64 %0, t; }" : "=r"(a) : "l"(p));
    return a;
}

__device__ __forceinline__ void ldsm_x4(uint32_t r[4], uint32_t addr) {
    asm volatile("ldmatrix.sync.aligned.m8n8.x4.shared.b16 {%0,%1,%2,%3}, [%4];"
                 : "=r"(r[0]), "=r"(r[1]), "=r"(r[2]), "=r"(r[3]) : "r"(addr));
}

__device__ __forceinline__ void mma16816(float c[4], const uint32_t a[4],
                                         uint32_t b0, uint32_t b1) {
    asm volatile(
        "mma.sync.aligned.m16n8k16.row.col.f32.f16.f16.f32 "
        "{%0,%1,%2,%3},{%4,%5,%6,%7},{%8,%9},{%0,%1,%2,%3};"
        : "+f"(c[0]), "+f"(c[1]), "+f"(c[2]), "+f"(c[3])
        : "r"(a[0]), "r"(a[1]), "r"(a[2]), "r"(a[3]), "r"(b0), "r"(b1));
}

__device__ __forceinline__ int load_idx(const void* p, long long i) {
    if (g_is64) return (int)((const long long*)p)[i];
    return ((const int*)p)[i];
}

__global__ void detect_kernel(const int* e) {
    if (threadIdx.x == 0) {
        int is64 = 1;
        for (int i = 1; i < 256; i += 2)
            if (e[i] != 0) { is64 = 0; break; }
        g_is64 = is64;
    }
}

__global__ void idx_kernel(const void* __restrict__ eidx) {
    int i = blockIdx.x * blockDim.x + threadIdx.x;
    if (i >= EE) return;
    g_srcA[i] = load_idx(eidx, i);
    int d = load_idx(eidx, (long long)EE + i);
    g_dstA[i] = d;
    atomicAdd(&g_degi[d], 1);
}

__global__ void scan_kernel() {
    __shared__ int s[1024];
    __shared__ int srun;
    int tid = threadIdx.x;
    if (tid == 0) srun = 0;
    __syncthreads();
    for (int c = 0; c < NN; c += 1024) {
        int v = g_degi[c + tid];
        s[tid] = v;
        __syncthreads();
        for (int off = 1; off < 1024; off <<= 1) {
            int t = (tid >= off) ? s[tid - off] : 0;
            __syncthreads();
            s[tid] += t;
            __syncthreads();
        }
        int excl = srun + s[tid] - v;
        g_rowp[c + tid] = excl;
        g_cursor[c + tid] = excl;
        __syncthreads();
        if (tid == 0) srun += s[1023];
        __syncthreads();
    }
    if (tid == 0) g_rowp[NN] = srun;
}

__global__ void fill_kernel() {
    int i = blockIdx.x * blockDim.x + threadIdx.x;
    if (i >= EE) return;
    int pos = atomicAdd(&g_cursor[g_dstA[i]], 1);
    g_csrs[pos] = g_srcA[i];
}

// ---------------------------------------------------------------------------
// Mf = mW2 @ uW1_bot (per layer, fp32), v = mb2 @ uW1_bot
// ---------------------------------------------------------------------------
__global__ void mf_kernel(const float* __restrict__ msgW2, const float* __restrict__ updW1,
                          const float* __restrict__ msgb2) {
    __shared__ float As[128 * 33];
    __shared__ float Bs[32 * 128];
    int l = blockIdx.x;
    const float* A = msgW2 + (size_t)l * 128 * 128;
    const float* B = updW1 + (size_t)l * 256 * 128 + 128 * 128;  // bottom half
    float* C = g_mfw + (size_t)l * 16384;
    int tid = threadIdx.x, tx = tid & 15, ty = tid >> 4;
    float acc[8][8];
#pragma unroll
    for (int i = 0; i < 8; i++)
#pragma unroll
        for (int j = 0; j < 8; j++) acc[i][j] = 0.f;

    for (int kc = 0; kc < 128; kc += 32) {
        for (int t = tid; t < 128 * 32; t += 256) {
            int r = t >> 5, c = t & 31;
            As[r * 33 + c] = A[r * 128 + kc + c];
        }
        for (int t = tid; t < 32 * 128; t += 256) {
            int r = t >> 7, c = t & 127;
            Bs[t] = B[(kc + r) * 128 + c];
        }
        __syncthreads();
#pragma unroll
        for (int k = 0; k < 32; k++) {
            float a[8], b[8];
#pragma unroll
            for (int i = 0; i < 8; i++) a[i] = As[(ty * 8 + i) * 33 + k];
#pragma unroll
            for (int j = 0; j < 8; j++) b[j] = Bs[k * 128 + tx * 8 + j];
#pragma unroll
            for (int i = 0; i < 8; i++)
#pragma unroll
                for (int j = 0; j < 8; j++) acc[i][j] += a[i] * b[j];
        }
        __syncthreads();
    }
#pragma unroll
    for (int i = 0; i < 8; i++)
#pragma unroll
        for (int j = 0; j < 8; j++)
            C[(ty * 8 + i) * 128 + tx * 8 + j] = acc[i][j];

    if (tid < 128) {
        float s = 0.f;
        for (int j = 0; j < 128; j++)
            s += msgb2[l * 128 + j] * B[j * 128 + tid];
        g_vb[l * 128 + tid] = s;
    }
}

// ---------------------------------------------------------------------------
// weight prep: fp32 [k][n] -> fragment-order fp16 image
// ---------------------------------------------------------------------------
__global__ void prep_fragk(const float* __restrict__ src, __half* __restrict__ dst,
                           int Ktrue, int Ntrue, int srcWidth,
                           int srcStride, int dstStride) {
    int l = blockIdx.x, ks = blockIdx.y;
    src += (size_t)l * srcStride;
    dst += (size_t)l * dstStride + (size_t)ks * 2048;
    int tid = threadIdx.x;
    int lane = tid & 31, p = (tid >> 5) & 3, wn = (tid >> 7) & 1;
    uint4 v;
    __half* hv = (__half*)&v;
#pragma unroll
    for (int h = 0; h < 8; h++) {
        int k = ks * 16 + (lane & 3) * 2 + (h & 1) + ((h >> 1) & 1) * 8;
        int n = wn * 64 + p * 16 + (lane >> 2) + (h >> 2) * 8;
        hv[h] = (k < Ktrue && n < Ntrue) ? __float2half(src[k * srcWidth + n]) : __half(0.f);
    }
    ((uint4*)dst)[tid] = v;
}

// ---------------------------------------------------------------------------
// HMMA core
// ---------------------------------------------------------------------------
struct MlpCtx {
    uint32_t sb;
    int lane, wm, wn;
    float acc[2][8][4];
};

__device__ __forceinline__ void gemm_zero(MlpCtx& c) {
#pragma unroll
    for (int mt = 0; mt < 2; mt++)
#pragma unroll
        for (int nt = 0; nt < 8; nt++)
#pragma unroll
            for (int q = 0; q < 4; q++) c.acc[mt][nt][q] = 0.f;
}

__device__ __forceinline__ void gemm_run(MlpCtx& c, uint32_t aoff, uint32_t pbytes,
                                         const uint4* __restrict__ wf, int ksteps) {
    int l = c.lane;
    uint32_t aBase = c.sb + aoff +
        (uint32_t)(c.wm * 32 + (l & 7) + ((l >> 3) & 1) * 8) * pbytes + (l >> 4) * 16;
    const uint4* wb = wf + c.wn * 128 + l;
#pragma unroll
    for (int ks = 0; ks < 16; ks++) {
        if (ks >= ksteps) break;
        uint32_t a0[4], a1[4];
        uint4 q[4];
#pragma unroll
        for (int p = 0; p < 4; p++) q[p] = __ldg(wb + ks * 256 + p * 32);
        ldsm_x4(a0, aBase + ks * 32);
        ldsm_x4(a1, aBase + 16 * pbytes + ks * 32);
#pragma unroll
        for (int p = 0; p < 4; p++) {
            mma16816(c.acc[0][2 * p],     a0, q[p].x, q[p].y);
            mma16816(c.acc[0][2 * p + 1], a0, q[p].z, q[p].w);
            mma16816(c.acc[1][2 * p],     a1, q[p].x, q[p].y);
            mma16816(c.acc[1][2 * p + 1], a1, q[p].z, q[p].w);
        }
    }
}

__device__ __forceinline__ void epi_relu_h(MlpCtx& c, char* sm, int shOff, int b1Off) {
    int g = c.lane >> 2, t = c.lane & 3;
    const float* sb1 = (const float*)(sm + b1Off);
#pragma unroll
    for (int mt = 0; mt < 2; mt++)
#pragma unroll
        for (int nt = 0; nt < 8; nt++) {
            int row = c.wm * 32 + mt * 16 + g;
            int col = c.wn * 64 + nt * 8 + t * 2;
            float v0 = c.acc[mt][nt][0] + sb1[col];
            float v1 = c.acc[mt][nt][1] + sb1[col + 1];
            float v2 = c.acc[mt][nt][2] + sb1[col];
            float v3 = c.acc[mt][nt][3] + sb1[col + 1];
            v0 = v0 > 0.f ? v0 : 0.f; v1 = v1 > 0.f ? v1 : 0.f;
            v2 = v2 > 0.f ? v2 : 0.f; v3 = v3 > 0.f ? v3 : 0.f;
            *(__half2*)(sm + shOff + row * (PB * 2) + col * 2) = __floats2half2_rn(v0, v1);
            *(__half2*)(sm + shOff + (row + 8) * (PB * 2) + col * 2) = __floats2half2_rn(v2, v3);
        }
}

// hidden epilogue with per-row deg*v bias: relu(acc + b1[col] + deg[row]*v[col])
__device__ __forceinline__ void epi_relu_hv(MlpCtx& c, char* sm) {
    int g = c.lane >> 2, t = c.lane & 3;
    const float* sb1 = (const float*)(sm + SB1_OFF);
    const float* sv  = (const float*)(sm + SB3_OFF);
    const float* sdg = (const float*)(sm + SDG_OFF);
#pragma unroll
    for (int mt = 0; mt < 2; mt++)
#pragma unroll
        for (int nt = 0; nt < 8; nt++) {
            int row = c.wm * 32 + mt * 16 + g;
            int col = c.wn * 64 + nt * 8 + t * 2;
            float d0 = sdg[row], d1 = sdg[row + 8];
            float v0 = c.acc[mt][nt][0] + sb1[col]     + d0 * sv[col];
            float v1 = c.acc[mt][nt][1] + sb1[col + 1] + d0 * sv[col + 1];
            float v2 = c.acc[mt][nt][2] + sb1[col]     + d1 * sv[col];
            float v3 = c.acc[mt][nt][3] + sb1[col + 1] + d1 * sv[col + 1];
            v0 = v0 > 0.f ? v0 : 0.f; v1 = v1 > 0.f ? v1 : 0.f;
            v2 = v2 > 0.f ? v2 : 0.f; v3 = v3 > 0.f ? v3 : 0.f;
            *(__half2*)(sm + SH_OFF + row * (PB * 2) + col * 2) = __floats2half2_rn(v0, v1);
            *(__half2*)(sm + SH_OFF + (row + 8) * (PB * 2) + col * 2) = __floats2half2_rn(v2, v3);
        }
}

__device__ __forceinline__ void epi_write_x_stage(MlpCtx& c, char* sm, int b2Off,
                                                  __half* __restrict__ xout, int n0,
                                                  int stageOff, bool doStage) {
    int g = c.lane >> 2, t = c.lane & 3;
    const float* sb2 = (const float*)(sm + b2Off);
#pragma unroll
    for (int mt = 0; mt < 2; mt++)
#pragma unroll
        for (int nt = 0; nt < 8; nt++) {
            int row = c.wm * 32 + mt * 16 + g;
            int col = c.wn * 64 + nt * 8 + t * 2;
            float bb0 = sb2[col], bb1 = sb2[col + 1];
            __half2 h0 = __floats2half2_rn(c.acc[mt][nt][0] + bb0, c.acc[mt][nt][1] + bb1);
            __half2 h1 = __floats2half2_rn(c.acc[mt][nt][2] + bb0, c.acc[mt][nt][3] + bb1);
            *(__half2*)(xout + (size_t)(n0 + row) * HH + col) = h0;
            *(__half2*)(xout + (size_t)(n0 + row + 8) * HH + col) = h1;
            if (doStage) {
                *(__half2*)(sm + stageOff + row * (PB * 2) + col * 2) = h0;
                *(__half2*)(sm + stageOff + (row + 8) * (PB * 2) + col * 2) = h1;
            }
        }
}

__device__ __forceinline__ void epi_write_gb(MlpCtx& c, __half* __restrict__ pout, int n0,
                                             const float* __restrict__ bias) {
    int g = c.lane >> 2, t = c.lane & 3;
#pragma unroll
    for (int mt = 0; mt < 2; mt++)
#pragma unroll
        for (int nt = 0; nt < 8; nt++) {
            int row = c.wm * 32 + mt * 16 + g;
            int col = c.wn * 64 + nt * 8 + t * 2;
            float bb0 = 0.f, bb1 = 0.f;
            if (bias) { bb0 = __ldg(bias + col); bb1 = __ldg(bias + col + 1); }
            __half2 h0 = __floats2half2_rn(c.acc[mt][nt][0] + bb0, c.acc[mt][nt][1] + bb1);
            __half2 h1 = __floats2half2_rn(c.acc[mt][nt][2] + bb0, c.acc[mt][nt][3] + bb1);
            *(__half2*)(pout + (size_t)(n0 + row) * HH + col) = h0;
            *(__half2*)(pout + (size_t)(n0 + row + 8) * HH + col) = h1;
        }
}

__device__ __forceinline__ void pre_from_stage(MlpCtx& c, uint32_t aoff,
                                               const uint4* __restrict__ nW1f,
                                               const float* __restrict__ nb1,
                                               __half* __restrict__ pd,
                                               __half* __restrict__ ps, int n0) {
    gemm_zero(c);
    gemm_run(c, aoff, PB * 2, nW1f, 8);
    epi_write_gb(c, pd, n0, nb1);
    gemm_zero(c);
    gemm_run(c, aoff, PB * 2, nW1f + 2048, 8);
    epi_write_gb(c, ps, n0, (const float*)0);
}

// ---------------------------------------------------------------------------
// CSR aggregation: one warp per node; full-warp uint2 (8B/lane), 4 edges in flight
// ---------------------------------------------------------------------------
__global__ void __launch_bounds__(256)
agg_csr(const __half* __restrict__ pd, const __half* __restrict__ ps,
        const int* __restrict__ csrs, const int* __restrict__ rowp,
        __half* __restrict__ aggH) {
    int w = (blockIdx.x * 256 + threadIdx.x) >> 5;
    int lane = threadIdx.x & 31;
    int beg = __ldg(rowp + w), end = __ldg(rowp + w + 1);

    uint2 pdu = __ldg((const uint2*)(pd + (size_t)w * HH) + lane);
    float2 p0 = __half22float2(*(__half2*)&pdu.x);
    float2 p1 = __half22float2(*(__half2*)&pdu.y);
    float a0 = 0.f, a1 = 0.f, a2 = 0.f, a3 = 0.f;

    int i = beg;
    for (; i + 3 < end; i += 4) {
        int s0 = __ldg(csrs + i),     s1 = __ldg(csrs + i + 1);
        int s2 = __ldg(csrs + i + 2), s3 = __ldg(csrs + i + 3);
        uint2 v0 = __ldg((const uint2*)(ps + (size_t)s0 * HH) + lane);
        uint2 v1 = __ldg((const uint2*)(ps + (size_t)s1 * HH) + lane);
        uint2 v2 = __ldg((const uint2*)(ps + (size_t)s2 * HH) + lane);
        uint2 v3 = __ldg((const uint2*)(ps + (size_t)s3 * HH) + lane);
#define ACCUM(v) do {                                           \
        float2 q0 = __half22float2(*(__half2*)&(v).x);          \
        float2 q1 = __half22float2(*(__half2*)&(v).y);          \
        a0 += fmaxf(p0.x + q0.x, 0.f);                          \
        a1 += fmaxf(p0.y + q0.y, 0.f);                          \
        a2 += fmaxf(p1.x + q1.x, 0.f);                          \
        a3 += fmaxf(p1.y + q1.y, 0.f); } while (0)
        ACCUM(v0); ACCUM(v1); ACCUM(v2); ACCUM(v3);
    }
    for (; i < end; i++) {
        int s0 = __ldg(csrs + i);
        uint2 v0 = __ldg((const uint2*)(ps + (size_t)s0 * HH) + lane);
        ACCUM(v0);
    }
#undef ACCUM
    __half2 o0 = __floats2half2_rn(a0, a1);
    __half2 o1 = __floats2half2_rn(a2, a3);
    uint2 ov;
    ov.x = *(uint32_t*)&o0; ov.y = *(uint32_t*)&o1;
    ((uint2*)(aggH + (size_t)w * HH))[lane] = ov;
}

// ---------------------------------------------------------------------------
// upd kernel: hidden = relu(x@uW1t + aggH@Mf + ub1 + deg*v); x2 = hidden@uW2+ub2
// fused next-layer pre
// ---------------------------------------------------------------------------
__global__ void __launch_bounds__(256, 2)
upd_tc(const __half* __restrict__ xh, const __half* __restrict__ aggH,
       const uint4* __restrict__ Mff, const float* __restrict__ vb,
       const int* __restrict__ degi,
       const uint4* __restrict__ wf1, const uint4* __restrict__ wf2,
       const float* __restrict__ b1, const float* __restrict__ b2,
       __half* __restrict__ xout,
       const uint4* __restrict__ nW1f, const float* __restrict__ nb1,
       __half* __restrict__ pd, __half* __restrict__ ps, int do_pre) {
    extern __shared__ __align__(128) char sm[];
    MlpCtx c;
    c.sb = smem_u32(sm);
    int tid = threadIdx.x;
    c.lane = tid & 31;
    int warp = tid >> 5;
    c.wm = warp >> 1; c.wn = warp & 1;
    int n0 = blockIdx.x * 128;

    if (tid < 128) {
        ((float*)(sm + SB1_OFF))[tid] = b1[tid];
        ((float*)(sm + SB2_OFF))[tid] = b2[tid];
        ((float*)(sm + SB3_OFF))[tid] = vb[tid];
        ((float*)(sm + SDG_OFF))[tid] = (float)degi[n0 + tid];
    }
    {
        int r = tid >> 1, h = tid & 1;
        int node = n0 + r;
        const uint4* row = (const uint4*)((h ? aggH : xh) + (size_t)node * HH);
        uint4* dstp = (uint4*)(sm + (h ? SG_OFF : SX_OFF) + r * (PB * 2));
#pragma unroll
        for (int j = 0; j < 16; j++) dstp[j] = __ldg(row + j);
    }
    __syncthreads();

    gemm_zero(c);
    gemm_run(c, SX_OFF, PB * 2, wf1, 8);
    gemm_run(c, SG_OFF, PB * 2, Mff, 8);
    epi_relu_hv(c, sm);
    __syncthreads();

    gemm_zero(c);
    gemm_run(c, SH_OFF, PB * 2, wf2, 8);
    epi_write_x_stage(c, sm, SB2_OFF, xout, n0, SX_OFF, do_pre != 0);

    if (do_pre) {
        __syncthreads();
        pre_from_stage(c, SX_OFF, nW1f, nb1, pd, ps, n0);
    }
}

// ---------------------------------------------------------------------------
// embed via HMMA + fused layer-0 pre
// ---------------------------------------------------------------------------
__global__ void __launch_bounds__(256, 2)
embed_tc(const float* __restrict__ loc, const float* __restrict__ vel,
         const uint4* __restrict__ wf1, const uint4* __restrict__ wf2,
         const float* __restrict__ b1, const float* __restrict__ b2,
         __half* __restrict__ xout,
         const uint4* __restrict__ nW1f, const float* __restrict__ nb1,
         __half* __restrict__ pd, __half* __restrict__ ps) {
    extern __shared__ __align__(128) char sm[];
    MlpCtx c;
    c.sb = smem_u32(sm);
    int tid = threadIdx.x;
    c.lane = tid & 31;
    int warp = tid >> 5;
    c.wm = warp >> 1; c.wn = warp & 1;
    int n0 = blockIdx.x * 128;

    if (tid < 128) {
        ((float*)(sm + EB1_OFF))[tid] = b1[tid];
        ((float*)(sm + EB2_OFF))[tid] = b2[tid];
    }
    if (tid < 128) {
        int r = tid;
        const float* lrow = loc + (size_t)(n0 + r) * 30;
        const float* vrow = vel + (size_t)(n0 + r) * 30;
        __half* drow = (__half*)(sm + EA_OFF + r * (PE * 2));
#pragma unroll
        for (int k = 0; k < 64; k++) {
            float v = 0.f;
            if (k < 60) {
                int f = k / 6, c6 = k % 6;
                v = (c6 < 3) ? lrow[f * 3 + c6] : vrow[f * 3 + c6 - 3];
            }
            drow[k] = __float2half(v);
        }
    }
    __syncthreads();

    gemm_zero(c);
    gemm_run(c, EA_OFF, PE * 2, wf1, 4);
    epi_relu_h(c, sm, EH_OFF, EB1_OFF);
    __syncthreads();

    gemm_zero(c);
    gemm_run(c, EH_OFF, PB * 2, wf2, 8);
    __syncthreads();
    epi_write_x_stage(c, sm, EB2_OFF, xout, n0, EH_OFF, true);
    __syncthreads();
    pre_from_stage(c, EH_OFF, nW1f, nb1, pd, ps, n0);
}

// ---------------------------------------------------------------------------
// head via HMMA
// ---------------------------------------------------------------------------
__global__ void __launch_bounds__(256, 2)
head_tc(const __half* __restrict__ xh,
        const uint4* __restrict__ wf1, const uint4* __restrict__ wf2,
        const float* __restrict__ b1, const float* __restrict__ b2,
        float* __restrict__ hout) {
    extern __shared__ __align__(128) char sm[];
    MlpCtx c;
    c.sb = smem_u32(sm);
    int tid = threadIdx.x;
    c.lane = tid & 31;
    int warp = tid >> 5;
    c.wm = warp >> 1; c.wn = warp & 1;
    int n0 = blockIdx.x * 128;

    if (tid < 128) ((float*)(sm + HB1_OFF))[tid] = b1[tid];
    if (tid < 30)  ((float*)(sm + HB2_OFF))[tid] = b2[tid];
    {
        int r = tid >> 1, h = tid & 1;
        const uint4* row = (const uint4*)xh + (size_t)(n0 + r) * 16 + h * 8;
        uint4* dstp = (uint4*)(sm + HA_OFF + r * (PB * 2)) + h * 8;
#pragma unroll
        for (int j = 0; j < 8; j++) dstp[j] = __ldg(row + j);
    }
    __syncthreads();

    gemm_zero(c);
    gemm_run(c, HA_OFF, PB * 2, wf1, 8);
    epi_relu_h(c, sm, HHS_OFF, HB1_OFF);
    __syncthreads();

    gemm_zero(c);
    gemm_run(c, HHS_OFF, PB * 2, wf2, 8);
    {
        int g = c.lane >> 2, t = c.lane & 3;
        const float* sb2 = (const float*)(sm + HB2_OFF);
        if (c.wn == 0) {
#pragma unroll
            for (int mt = 0; mt < 2; mt++)
#pragma unroll
                for (int nt = 0; nt < 4; nt++) {
                    int row = c.wm * 32 + mt * 16 + g;
                    int col = nt * 8 + t * 2;
                    if (col < 30) {
                        hout[(size_t)(n0 + row) * 30 + col] = c.acc[mt][nt][0] + sb2[col];
                        hout[(size_t)(n0 + row + 8) * 30 + col] = c.acc[mt][nt][2] + sb2[col];
                    }
                    if (col + 1 < 30) {
                        hout[(size_t)(n0 + row) * 30 + col + 1] = c.acc[mt][nt][1] + sb2[col + 1];
                        hout[(size_t)(n0 + row + 8) * 30 + col + 1] = c.acc[mt][nt][3] + sb2[col + 1];
                    }
                }
        }
    }
}

// ---------------------------------------------------------------------------
// loss
// ---------------------------------------------------------------------------
__global__ void loss_kernel(const float* __restrict__ hout, const float* __restrict__ loc,
                            const float* __restrict__ y, float* __restrict__ out) {
    int w = (blockIdx.x * blockDim.x + threadIdx.x) >> 5;
    int lane = threadIdx.x & 31;
    if (w >= BB) return;
    float ade = 0.f, fde = 0.f;
    for (int p = lane; p < 160; p += 32) {
        int node = w * 16 + p / NF;
        int f = p % NF;
        int base = node * 30 + f * 3;
        float dx = hout[base] + loc[base] - y[base];
        float dy = hout[base + 1] + loc[base + 1] - y[base + 1];
        float dz = hout[base + 2] + loc[base + 2] - y[base + 2];
        float d = sqrtf(dx * dx + dy * dy + dz * dz);
        ade += d;
        if (f == NF - 1) fde += d;
    }
#pragma unroll
    for (int o = 16; o; o >>= 1) {
        ade += __shfl_down_sync(0xffffffffu, ade, o);
        fde += __shfl_down_sync(0xffffffffu, fde, o);
    }
    if (lane == 0) {
        out[1 + w] = ade / 160.f;
        out[1 + BB + w] = fde / 16.f;
    }
}

__global__ void final_kernel(float* __restrict__ out) {
    __shared__ float s[256];
    float v = 0.f;
    for (int i = threadIdx.x; i < BB; i += 256) v += out[1 + i];
    s[threadIdx.x] = v;
    __syncthreads();
    for (int o = 128; o; o >>= 1) {
        if (threadIdx.x < o) s[threadIdx.x] += s[threadIdx.x + o];
        __syncthreads();
    }
    if (threadIdx.x == 0) out[0] = s[0] / (float)BB;
}

// ---------------------------------------------------------------------------
// host
// ---------------------------------------------------------------------------
extern "C" void kernel_launch(void* const* d_in, const int* in_sizes, int n_in,
                              void* d_out, int out_size) {
    int o = (n_in > 4 && in_sizes[4] == 1) ? 1 : 0;
    const float* loc = (const float*)d_in[0];
    const float* vel = (const float*)d_in[1];
    const float* y   = (const float*)d_in[2];
    const void*  eix = d_in[3];
    const float* embW1 = (const float*)d_in[4 + o];
    const float* embb1 = (const float*)d_in[5 + o];
    const float* embW2 = (const float*)d_in[6 + o];
    const float* embb2 = (const float*)d_in[7 + o];
    const float* msgW1 = (const float*)d_in[8 + o];
    const float* msgb1 = (const float*)d_in[9 + o];
    const float* msgW2 = (const float*)d_in[10 + o];
    const float* msgb2 = (const float*)d_in[11 + o];
    const float* updW1 = (const float*)d_in[12 + o];
    const float* updb1 = (const float*)d_in[13 + o];
    const float* updW2 = (const float*)d_in[14 + o];
    const float* updb2 = (const float*)d_in[15 + o];
    const float* hW1 = (const float*)d_in[16 + o];
    const float* hb1 = (const float*)d_in[17 + o];
    const float* hW2 = (const float*)d_in[18 + o];
    const float* hb2 = (const float*)d_in[19 + o];
    float* out = (float*)d_out;

    cudaFuncSetAttribute(upd_tc, cudaFuncAttributeMaxDynamicSharedMemorySize, DYNB_U);
    cudaFuncSetAttribute(embed_tc, cudaFuncAttributeMaxDynamicSharedMemorySize, DYNB_EM);
    cudaFuncSetAttribute(head_tc, cudaFuncAttributeMaxDynamicSharedMemorySize, DYNB_H);

    __half *xhp, *xh2p, *pdp, *psp, *agghp;
    float *headp, *mfwp, *vbp;
    int *degip, *csrsp, *rowpp;
    uint4 *mW1f, *Mff, *uW1f, *uW2f, *eW1f, *eW2f, *hW1f, *hW2f;
    cudaGetSymbolAddress((void**)&xhp, g_xh);
    cudaGetSymbolAddress((void**)&xh2p, g_xh2);
    cudaGetSymbolAddress((void**)&pdp, g_pd);
    cudaGetSymbolAddress((void**)&psp, g_ps);
    cudaGetSymbolAddress((void**)&agghp, g_aggh);
    cudaGetSymbolAddress((void**)&degip, g_degi);
    cudaGetSymbolAddress((void**)&headp, g_head);
    cudaGetSymbolAddress((void**)&csrsp, g_csrs);
    cudaGetSymbolAddress((void**)&rowpp, g_rowp);
    cudaGetSymbolAddress((void**)&mfwp, g_mfw);
    cudaGetSymbolAddress((void**)&vbp, g_vb);
    cudaGetSymbolAddress((void**)&mW1f, g_mW1f);
    cudaGetSymbolAddress((void**)&Mff, g_Mff);
    cudaGetSymbolAddress((void**)&uW1f, g_uW1f);
    cudaGetSymbolAddress((void**)&uW2f, g_uW2f);
    cudaGetSymbolAddress((void**)&eW1f, g_eW1f);
    cudaGetSymbolAddress((void**)&eW2f, g_eW2f);
    cudaGetSymbolAddress((void**)&hW1f, g_hW1f);
    cudaGetSymbolAddress((void**)&hW2f, g_hW2f);

    detect_kernel<<<1, 32>>>((const int*)eix);
    cudaMemsetAsync(degip, 0, NN * sizeof(int));
    idx_kernel<<<EE / 256, 256>>>(eix);
    scan_kernel<<<1, 1024>>>();
    fill_kernel<<<EE / 256, 256>>>();
    mf_kernel<<<LL, 256>>>(msgW2, updW1, msgb2);
    prep_fragk<<<dim3(LL, 16), 256>>>(msgW1, (__half*)mW1f, 256, 128, 128, 256 * 128, 32768);
    prep_fragk<<<dim3(LL, 16), 256>>>(updW1, (__half*)uW1f, 256, 128, 128, 256 * 128, 32768);
    prep_fragk<<<dim3(LL, 8), 256>>>(updW2, (__half*)uW2f, 128, 128, 128, 128 * 128, 16384);
    prep_fragk<<<dim3(LL, 8), 256>>>(mfwp, (__half*)Mff, 128, 128, 128, 16384, 16384);
    prep_fragk<<<dim3(1, 4), 256>>>(embW1, (__half*)eW1f, 60, 128, 128, 0, 0);
    prep_fragk<<<dim3(1, 8), 256>>>(embW2, (__half*)eW2f, 128, 128, 128, 0, 0);
    prep_fragk<<<dim3(1, 8), 256>>>(hW1, (__half*)hW1f, 128, 128, 128, 0, 0);
    prep_fragk<<<dim3(1, 8), 256>>>(hW2, (__half*)hW2f, 128, 30, 30, 0, 0);

    embed_tc<<<NN / 128, 256, DYNB_EM>>>(loc, vel, eW1f, eW2f, embb1, embb2, xhp,
                                         mW1f, msgb1, pdp, psp);

    __half* xa = xhp;
    __half* xb = xh2p;
    for (int i = 0; i < LL; i++) {
        agg_csr<<<NN / 8, 256>>>(pdp, psp, csrsp, rowpp, agghp);
        upd_tc<<<NN / 128, 256, DYNB_U>>>(
            xa, agghp,
            Mff + (size_t)i * 2048, vbp + (size_t)i * 128, degip,
            uW1f + (size_t)i * 4096, uW2f + (size_t)i * 2048,
            updb1 + (size_t)i * HH, updb2 + (size_t)i * HH, xb,
            mW1f + (size_t)(i + 1 < LL ? i + 1 : 0) * 4096,
            msgb1 + (size_t)(i + 1 < LL ? i + 1 : 0) * HH, pdp, psp,
            i + 1 < LL ? 1 : 0);
        __half* t = xa; xa = xb; xb = t;
    }
    head_tc<<<NN / 128, 256, DYNB_H>>>(xa, hW1f, hW2f, hb1, hb2, headp);
    loss_kernel<<<(BB * 32 + 127) / 128, 128>>>(headp, loc, y, out);
    final_kernel<<<1, 256>>>(out);
}

// round 17
// speedup vs baseline: 1.1386x; 1.1050x over previous
#include <cuda_runtime.h>
#include <cuda_fp16.h>
#include <math.h>
#include <stdint.h>

#define NN 32768
#define EE 524288
#define HH 128
#define BB 2048
#define LL 7
#define NF 10

// ---------------------------------------------------------------------------
// device scratch
// ---------------------------------------------------------------------------
__device__ int    g_is64;
__device__ __half g_xh[NN * HH];
__device__ __half g_xh2[NN * HH];
__device__ __half g_pd[NN * HH];
__device__ __half g_ps[NN * HH];
__device__ __half g_aggh[NN * HH];
__device__ int    g_degi[NN];
__device__ float  g_head[NN * 30];
__device__ int    g_srcA[EE];
__device__ int    g_dstA[EE];
__device__ int    g_csrs[EE];
__device__ int    g_rowp[NN + 1];
__device__ int    g_cursor[NN];
__device__ int    g_bsum[32];
__device__ int    g_boff[32];
__device__ float  g_mfw[LL * 16384];
__device__ float  g_vb[LL * 128];
__device__ uint4 g_mW1f[LL * 4096];
__device__ uint4 g_Mff[LL * 2048];
__device__ uint4 g_uW1f[LL * 4096];
__device__ uint4 g_uW2f[LL * 2048];
__device__ uint4 g_eW1f[1024];
__device__ uint4 g_eW2f[2048];
__device__ uint4 g_hW1f[2048];
__device__ uint4 g_hW2f[2048];

#define PB 136
#define PE 72

// ---- upd kernel smem ----
#define SX_OFF   0
#define SG_OFF   (128 * PB * 2)
#define SH_OFF   (2 * 128 * PB * 2)
#define SB1_OFF  (3 * 128 * PB * 2)              // 104448
#define SB2_OFF  (SB1_OFF + 512)
#define SB3_OFF  (SB2_OFF + 512)
#define SDG_OFF  (SB3_OFF + 512)
#define SB4_OFF  (SDG_OFF + 512)                 // aux b1 (next msgb1 / head b1)
#define SB5_OFF  (SB4_OFF + 512)                 // aux b2 (head b2)
#define DYNB_U   (SB5_OFF + 512)

// ---- embed smem ----
#define EA_OFF   0
#define EH_OFF   (128 * PE * 2)
#define EB1_OFF  (EH_OFF + 128 * PB * 2)
#define EB2_OFF  (EB1_OFF + 512)
#define DYNB_EM  (EB2_OFF + 512)

__device__ __forceinline__ uint32_t smem_u32(const void* p) {
    uint32_t a;
    asm("{ .reg .u64 t; cvta.to.shared.u64 t, %1; cvt.u32.u64 %0, t; }" : "=r"(a) : "l"(p));
    return a;
}

__device__ __forceinline__ void ldsm_x4(uint32_t r[4], uint32_t addr) {
    asm volatile("ldmatrix.sync.aligned.m8n8.x4.shared.b16 {%0,%1,%2,%3}, [%4];"
                 : "=r"(r[0]), "=r"(r[1]), "=r"(r[2]), "=r"(r[3]) : "r"(addr));
}

__device__ __forceinline__ void mma16816(float c[4], const uint32_t a[4],
                                         uint32_t b0, uint32_t b1) {
    asm volatile(
        "mma.sync.aligned.m16n8k16.row.col.f32.f16.f16.f32 "
        "{%0,%1,%2,%3},{%4,%5,%6,%7},{%8,%9},{%0,%1,%2,%3};"
        : "+f"(c[0]), "+f"(c[1]), "+f"(c[2]), "+f"(c[3])
        : "r"(a[0]), "r"(a[1]), "r"(a[2]), "r"(a[3]), "r"(b0), "r"(b1));
}

__device__ __forceinline__ int load_idx(const void* p, long long i) {
    if (g_is64) return (int)((const long long*)p)[i];
    return ((const int*)p)[i];
}

__global__ void detect_kernel(const int* e) {
    if (threadIdx.x == 0) {
        int is64 = 1;
        for (int i = 1; i < 256; i += 2)
            if (e[i] != 0) { is64 = 0; break; }
        g_is64 = is64;
    }
}

__global__ void idx_kernel(const void* __restrict__ eidx) {
    int i = blockIdx.x * blockDim.x + threadIdx.x;
    if (i >= EE) return;
    g_srcA[i] = load_idx(eidx, i);
    int d = load_idx(eidx, (long long)EE + i);
    g_dstA[i] = d;
    atomicAdd(&g_degi[d], 1);
}

// parallel 3-phase scan
__global__ void scanA_kernel() {
    __shared__ int s[1024];
    int b = blockIdx.x, tid = threadIdx.x;
    int i = b * 1024 + tid;
    int v = g_degi[i];
    s[tid] = v;
    __syncthreads();
    for (int off = 1; off < 1024; off <<= 1) {
        int t = (tid >= off) ? s[tid - off] : 0;
        __syncthreads();
        s[tid] += t;
        __syncthreads();
    }
    g_rowp[i] = s[tid] - v;          // block-local exclusive
    if (tid == 1023) g_bsum[b] = s[1023];
}
__global__ void scanB_kernel() {
    int tid = threadIdx.x;           // 32 threads
    int v = g_bsum[tid];
    int e = v;
#pragma unroll
    for (int off = 1; off < 32; off <<= 1) {
        int t = __shfl_up_sync(0xffffffffu, e, off);
        if (tid >= off) e += t;
    }
    g_boff[tid] = e - v;
    if (tid == 31) g_rowp[NN] = e;
}
__global__ void scanC_kernel() {
    int b = blockIdx.x, tid = threadIdx.x;
    int i = b * 1024 + tid;
    int r = g_rowp[i] + g_boff[b];
    g_rowp[i] = r;
    g_cursor[i] = r;
}

__global__ void fill_kernel() {
    int i = blockIdx.x * blockDim.x + threadIdx.x;
    if (i >= EE) return;
    int pos = atomicAdd(&g_cursor[g_dstA[i]], 1);
    g_csrs[pos] = g_srcA[i];
}

// ---------------------------------------------------------------------------
// Mf = mW2 @ uW1_bot (per layer, fp32), v = mb2 @ uW1_bot
// ---------------------------------------------------------------------------
__global__ void mf_kernel(const float* __restrict__ msgW2, const float* __restrict__ updW1,
                          const float* __restrict__ msgb2) {
    __shared__ float As[128 * 33];
    __shared__ float Bs[32 * 128];
    int l = blockIdx.x;
    const float* A = msgW2 + (size_t)l * 128 * 128;
    const float* B = updW1 + (size_t)l * 256 * 128 + 128 * 128;
    float* C = g_mfw + (size_t)l * 16384;
    int tid = threadIdx.x, tx = tid & 15, ty = tid >> 4;
    float acc[8][8];
#pragma unroll
    for (int i = 0; i < 8; i++)
#pragma unroll
        for (int j = 0; j < 8; j++) acc[i][j] = 0.f;

    for (int kc = 0; kc < 128; kc += 32) {
        for (int t = tid; t < 128 * 32; t += 256) {
            int r = t >> 5, c = t & 31;
            As[r * 33 + c] = A[r * 128 + kc + c];
        }
        for (int t = tid; t < 32 * 128; t += 256) {
            int r = t >> 7, c = t & 127;
            Bs[t] = B[(kc + r) * 128 + c];
        }
        __syncthreads();
#pragma unroll
        for (int k = 0; k < 32; k++) {
            float a[8], b[8];
#pragma unroll
            for (int i = 0; i < 8; i++) a[i] = As[(ty * 8 + i) * 33 + k];
#pragma unroll
            for (int j = 0; j < 8; j++) b[j] = Bs[k * 128 + tx * 8 + j];
#pragma unroll
            for (int i = 0; i < 8; i++)
#pragma unroll
                for (int j = 0; j < 8; j++) acc[i][j] += a[i] * b[j];
        }
        __syncthreads();
    }
#pragma unroll
    for (int i = 0; i < 8; i++)
#pragma unroll
        for (int j = 0; j < 8; j++)
            C[(ty * 8 + i) * 128 + tx * 8 + j] = acc[i][j];

    if (tid < 128) {
        float s = 0.f;
        for (int j = 0; j < 128; j++)
            s += msgb2[l * 128 + j] * B[j * 128 + tid];
        g_vb[l * 128 + tid] = s;
    }
}

// ---------------------------------------------------------------------------
// weight prep
// ---------------------------------------------------------------------------
__global__ void prep_fragk(const float* __restrict__ src, __half* __restrict__ dst,
                           int Ktrue, int Ntrue, int srcWidth,
                           int srcStride, int dstStride) {
    int l = blockIdx.x, ks = blockIdx.y;
    src += (size_t)l * srcStride;
    dst += (size_t)l * dstStride + (size_t)ks * 2048;
    int tid = threadIdx.x;
    int lane = tid & 31, p = (tid >> 5) & 3, wn = (tid >> 7) & 1;
    uint4 v;
    __half* hv = (__half*)&v;
#pragma unroll
    for (int h = 0; h < 8; h++) {
        int k = ks * 16 + (lane & 3) * 2 + (h & 1) + ((h >> 1) & 1) * 8;
        int n = wn * 64 + p * 16 + (lane >> 2) + (h >> 2) * 8;
        hv[h] = (k < Ktrue && n < Ntrue) ? __float2half(src[k * srcWidth + n]) : __half(0.f);
    }
    ((uint4*)dst)[tid] = v;
}

// ---------------------------------------------------------------------------
// HMMA core
// ---------------------------------------------------------------------------
struct MlpCtx {
    uint32_t sb;
    int lane, wm, wn;
    float acc[2][8][4];
};

__device__ __forceinline__ void gemm_zero(MlpCtx& c) {
#pragma unroll
    for (int mt = 0; mt < 2; mt++)
#pragma unroll
        for (int nt = 0; nt < 8; nt++)
#pragma unroll
            for (int q = 0; q < 4; q++) c.acc[mt][nt][q] = 0.f;
}

__device__ __forceinline__ void gemm_run(MlpCtx& c, uint32_t aoff, uint32_t pbytes,
                                         const uint4* __restrict__ wf, int ksteps) {
    int l = c.lane;
    uint32_t aBase = c.sb + aoff +
        (uint32_t)(c.wm * 32 + (l & 7) + ((l >> 3) & 1) * 8) * pbytes + (l >> 4) * 16;
    const uint4* wb = wf + c.wn * 128 + l;
#pragma unroll
    for (int ks = 0; ks < 16; ks++) {
        if (ks >= ksteps) break;
        uint32_t a0[4], a1[4];
        uint4 q[4];
#pragma unroll
        for (int p = 0; p < 4; p++) q[p] = __ldg(wb + ks * 256 + p * 32);
        ldsm_x4(a0, aBase + ks * 32);
        ldsm_x4(a1, aBase + 16 * pbytes + ks * 32);
#pragma unroll
        for (int p = 0; p < 4; p++) {
            mma16816(c.acc[0][2 * p],     a0, q[p].x, q[p].y);
            mma16816(c.acc[0][2 * p + 1], a0, q[p].z, q[p].w);
            mma16816(c.acc[1][2 * p],     a1, q[p].x, q[p].y);
            mma16816(c.acc[1][2 * p + 1], a1, q[p].z, q[p].w);
        }
    }
}

__device__ __forceinline__ void epi_relu_h(MlpCtx& c, char* sm, int shOff, int b1Off) {
    int g = c.lane >> 2, t = c.lane & 3;
    const float* sb1 = (const float*)(sm + b1Off);
#pragma unroll
    for (int mt = 0; mt < 2; mt++)
#pragma unroll
        for (int nt = 0; nt < 8; nt++) {
            int row = c.wm * 32 + mt * 16 + g;
            int col = c.wn * 64 + nt * 8 + t * 2;
            float v0 = c.acc[mt][nt][0] + sb1[col];
            float v1 = c.acc[mt][nt][1] + sb1[col + 1];
            float v2 = c.acc[mt][nt][2] + sb1[col];
            float v3 = c.acc[mt][nt][3] + sb1[col + 1];
            v0 = v0 > 0.f ? v0 : 0.f; v1 = v1 > 0.f ? v1 : 0.f;
            v2 = v2 > 0.f ? v2 : 0.f; v3 = v3 > 0.f ? v3 : 0.f;
            *(__half2*)(sm + shOff + row * (PB * 2) + col * 2) = __floats2half2_rn(v0, v1);
            *(__half2*)(sm + shOff + (row + 8) * (PB * 2) + col * 2) = __floats2half2_rn(v2, v3);
        }
}

__device__ __forceinline__ void epi_relu_hv(MlpCtx& c, char* sm) {
    int g = c.lane >> 2, t = c.lane & 3;
    const float* sb1 = (const float*)(sm + SB1_OFF);
    const float* sv  = (const float*)(sm + SB3_OFF);
    const float* sdg = (const float*)(sm + SDG_OFF);
#pragma unroll
    for (int mt = 0; mt < 2; mt++)
#pragma unroll
        for (int nt = 0; nt < 8; nt++) {
            int row = c.wm * 32 + mt * 16 + g;
            int col = c.wn * 64 + nt * 8 + t * 2;
            float d0 = sdg[row], d1 = sdg[row + 8];
            float v0 = c.acc[mt][nt][0] + sb1[col]     + d0 * sv[col];
            float v1 = c.acc[mt][nt][1] + sb1[col + 1] + d0 * sv[col + 1];
            float v2 = c.acc[mt][nt][2] + sb1[col]     + d1 * sv[col];
            float v3 = c.acc[mt][nt][3] + sb1[col + 1] + d1 * sv[col + 1];
            v0 = v0 > 0.f ? v0 : 0.f; v1 = v1 > 0.f ? v1 : 0.f;
            v2 = v2 > 0.f ? v2 : 0.f; v3 = v3 > 0.f ? v3 : 0.f;
            *(__half2*)(sm + SH_OFF + row * (PB * 2) + col * 2) = __floats2half2_rn(v0, v1);
            *(__half2*)(sm + SH_OFF + (row + 8) * (PB * 2) + col * 2) = __floats2half2_rn(v2, v3);
        }
}

__device__ __forceinline__ void epi_write_x_stage(MlpCtx& c, char* sm, int b2Off,
                                                  __half* __restrict__ xout, int n0,
                                                  int stageOff, bool doStage) {
    int g = c.lane >> 2, t = c.lane & 3;
    const float* sb2 = (const float*)(sm + b2Off);
#pragma unroll
    for (int mt = 0; mt < 2; mt++)
#pragma unroll
        for (int nt = 0; nt < 8; nt++) {
            int row = c.wm * 32 + mt * 16 + g;
            int col = c.wn * 64 + nt * 8 + t * 2;
            float bb0 = sb2[col], bb1 = sb2[col + 1];
            __half2 h0 = __floats2half2_rn(c.acc[mt][nt][0] + bb0, c.acc[mt][nt][1] + bb1);
            __half2 h1 = __floats2half2_rn(c.acc[mt][nt][2] + bb0, c.acc[mt][nt][3] + bb1);
            *(__half2*)(xout + (size_t)(n0 + row) * HH + col) = h0;
            *(__half2*)(xout + (size_t)(n0 + row + 8) * HH + col) = h1;
            if (doStage) {
                *(__half2*)(sm + stageOff + row * (PB * 2) + col * 2) = h0;
                *(__half2*)(sm + stageOff + (row + 8) * (PB * 2) + col * 2) = h1;
            }
        }
}

__device__ __forceinline__ void epi_write_gb(MlpCtx& c, __half* __restrict__ pout, int n0,
                                             const float* __restrict__ bias) {
    int g = c.lane >> 2, t = c.lane & 3;
#pragma unroll
    for (int mt = 0; mt < 2; mt++)
#pragma unroll
        for (int nt = 0; nt < 8; nt++) {
            int row = c.wm * 32 + mt * 16 + g;
            int col = c.wn * 64 + nt * 8 + t * 2;
            float bb0 = 0.f, bb1 = 0.f;
            if (bias) { bb0 = __ldg(bias + col); bb1 = __ldg(bias + col + 1); }
            __half2 h0 = __floats2half2_rn(c.acc[mt][nt][0] + bb0, c.acc[mt][nt][1] + bb1);
            __half2 h1 = __floats2half2_rn(c.acc[mt][nt][2] + bb0, c.acc[mt][nt][3] + bb1);
            *(__half2*)(pout + (size_t)(n0 + row) * HH + col) = h0;
            *(__half2*)(pout + (size_t)(n0 + row + 8) * HH + col) = h1;
        }
}

__device__ __forceinline__ void pre_from_stage(MlpCtx& c, uint32_t aoff,
                                               const uint4* __restrict__ nW1f,
                                               const float* __restrict__ nb1,
                                               __half* __restrict__ pd,
                                               __half* __restrict__ ps, int n0) {
    gemm_zero(c);
    gemm_run(c, aoff, PB * 2, nW1f, 8);
    epi_write_gb(c, pd, n0, nb1);
    gemm_zero(c);
    gemm_run(c, aoff, PB * 2, nW1f + 2048, 8);
    epi_write_gb(c, ps, n0, (const float*)0);
}

// ---------------------------------------------------------------------------
// CSR aggregation (unchanged from R16)
// ---------------------------------------------------------------------------
__global__ void __launch_bounds__(256)
agg_csr(const __half* __restrict__ pd, const __half* __restrict__ ps,
        const int* __restrict__ csrs, const int* __restrict__ rowp,
        __half* __restrict__ aggH) {
    int w = (blockIdx.x * 256 + threadIdx.x) >> 5;
    int lane = threadIdx.x & 31;
    int beg = __ldg(rowp + w), end = __ldg(rowp + w + 1);

    uint2 pdu = __ldg((const uint2*)(pd + (size_t)w * HH) + lane);
    float2 p0 = __half22float2(*(__half2*)&pdu.x);
    float2 p1 = __half22float2(*(__half2*)&pdu.y);
    float a0 = 0.f, a1 = 0.f, a2 = 0.f, a3 = 0.f;

    int i = beg;
    for (; i + 3 < end; i += 4) {
        int s0 = __ldg(csrs + i),     s1 = __ldg(csrs + i + 1);
        int s2 = __ldg(csrs + i + 2), s3 = __ldg(csrs + i + 3);
        uint2 v0 = __ldg((const uint2*)(ps + (size_t)s0 * HH) + lane);
        uint2 v1 = __ldg((const uint2*)(ps + (size_t)s1 * HH) + lane);
        uint2 v2 = __ldg((const uint2*)(ps + (size_t)s2 * HH) + lane);
        uint2 v3 = __ldg((const uint2*)(ps + (size_t)s3 * HH) + lane);
#define ACCUM(v) do {                                           \
        float2 q0 = __half22float2(*(__half2*)&(v).x);          \
        float2 q1 = __half22float2(*(__half2*)&(v).y);          \
        a0 += fmaxf(p0.x + q0.x, 0.f);                          \
        a1 += fmaxf(p0.y + q0.y, 0.f);                          \
        a2 += fmaxf(p1.x + q1.x, 0.f);                          \
        a3 += fmaxf(p1.y + q1.y, 0.f); } while (0)
        ACCUM(v0); ACCUM(v1); ACCUM(v2); ACCUM(v3);
    }
    for (; i < end; i++) {
        int s0 = __ldg(csrs + i);
        uint2 v0 = __ldg((const uint2*)(ps + (size_t)s0 * HH) + lane);
        ACCUM(v0);
    }
#undef ACCUM
    __half2 o0 = __floats2half2_rn(a0, a1);
    __half2 o1 = __floats2half2_rn(a2, a3);
    uint2 ov;
    ov.x = *(uint32_t*)&o0; ov.y = *(uint32_t*)&o1;
    ((uint2*)(aggH + (size_t)w * HH))[lane] = ov;
}

// ---------------------------------------------------------------------------
// upd kernel: hidden = relu(x@uW1t + aggH@Mf + ub1 + deg*v); x2 = hidden@uW2+ub2
// tail: mode 1 -> next-layer pre ; mode 2 -> head MLP
// ---------------------------------------------------------------------------
__global__ void __launch_bounds__(256, 2)
upd_tc(const __half* __restrict__ xh, const __half* __restrict__ aggH,
       const uint4* __restrict__ Mff, const float* __restrict__ vb,
       const int* __restrict__ degi,
       const uint4* __restrict__ wf1, const uint4* __restrict__ wf2,
       const float* __restrict__ b1, const float* __restrict__ b2,
       __half* __restrict__ xout,
       const uint4* __restrict__ auxW1, const uint4* __restrict__ auxW2,
       const float* __restrict__ auxb1, const float* __restrict__ auxb2,
       __half* __restrict__ pd, __half* __restrict__ ps,
       float* __restrict__ hout, int mode) {
    extern __shared__ __align__(128) char sm[];
    MlpCtx c;
    c.sb = smem_u32(sm);
    int tid = threadIdx.x;
    c.lane = tid & 31;
    int warp = tid >> 5;
    c.wm = warp >> 1; c.wn = warp & 1;
    int n0 = blockIdx.x * 128;

    if (tid < 128) {
        ((float*)(sm + SB1_OFF))[tid] = b1[tid];
        ((float*)(sm + SB2_OFF))[tid] = b2[tid];
        ((float*)(sm + SB3_OFF))[tid] = vb[tid];
        ((float*)(sm + SDG_OFF))[tid] = (float)degi[n0 + tid];
        ((float*)(sm + SB4_OFF))[tid] = auxb1[tid];
        ((float*)(sm + SB5_OFF))[tid] = (mode == 2 && tid < 30) ? auxb2[tid] : 0.f;
    }
    {
        int r = tid >> 1, h = tid & 1;
        int node = n0 + r;
        const uint4* row = (const uint4*)((h ? aggH : xh) + (size_t)node * HH);
        uint4* dstp = (uint4*)(sm + (h ? SG_OFF : SX_OFF) + r * (PB * 2));
#pragma unroll
        for (int j = 0; j < 16; j++) dstp[j] = __ldg(row + j);
    }
    __syncthreads();

    gemm_zero(c);
    gemm_run(c, SX_OFF, PB * 2, wf1, 8);
    gemm_run(c, SG_OFF, PB * 2, Mff, 8);
    epi_relu_hv(c, sm);
    __syncthreads();

    gemm_zero(c);
    gemm_run(c, SH_OFF, PB * 2, wf2, 8);
    epi_write_x_stage(c, sm, SB2_OFF, xout, n0, SX_OFF, mode != 0);

    if (mode == 1) {
        __syncthreads();
        pre_from_stage(c, SX_OFF, auxW1, auxb1, pd, ps, n0);
    } else if (mode == 2) {
        __syncthreads();
        // head: relu(x2 @ hW1 + hb1) @ hW2 + hb2 -> hout (cols < 30)
        gemm_zero(c);
        gemm_run(c, SX_OFF, PB * 2, auxW1, 8);
        epi_relu_h(c, sm, SH_OFF, SB4_OFF);
        __syncthreads();
        gemm_zero(c);
        gemm_run(c, SH_OFF, PB * 2, auxW2, 8);
        {
            int g = c.lane >> 2, t = c.lane & 3;
            const float* sb5 = (const float*)(sm + SB5_OFF);
            if (c.wn == 0) {
#pragma unroll
                for (int mt = 0; mt < 2; mt++)
#pragma unroll
                    for (int nt = 0; nt < 4; nt++) {
                        int row = c.wm * 32 + mt * 16 + g;
                        int col = nt * 8 + t * 2;
                        if (col < 30) {
                            hout[(size_t)(n0 + row) * 30 + col] = c.acc[mt][nt][0] + sb5[col];
                            hout[(size_t)(n0 + row + 8) * 30 + col] = c.acc[mt][nt][2] + sb5[col];
                        }
                        if (col + 1 < 30) {
                            hout[(size_t)(n0 + row) * 30 + col + 1] = c.acc[mt][nt][1] + sb5[col + 1];
                            hout[(size_t)(n0 + row + 8) * 30 + col + 1] = c.acc[mt][nt][3] + sb5[col + 1];
                        }
                    }
            }
        }
    }
}

// ---------------------------------------------------------------------------
// embed via HMMA + fused layer-0 pre
// ---------------------------------------------------------------------------
__global__ void __launch_bounds__(256, 2)
embed_tc(const float* __restrict__ loc, const float* __restrict__ vel,
         const uint4* __restrict__ wf1, const uint4* __restrict__ wf2,
         const float* __restrict__ b1, const float* __restrict__ b2,
         __half* __restrict__ xout,
         const uint4* __restrict__ nW1f, const float* __restrict__ nb1,
         __half* __restrict__ pd, __half* __restrict__ ps) {
    extern __shared__ __align__(128) char sm[];
    MlpCtx c;
    c.sb = smem_u32(sm);
    int tid = threadIdx.x;
    c.lane = tid & 31;
    int warp = tid >> 5;
    c.wm = warp >> 1; c.wn = warp & 1;
    int n0 = blockIdx.x * 128;

    if (tid < 128) {
        ((float*)(sm + EB1_OFF))[tid] = b1[tid];
        ((float*)(sm + EB2_OFF))[tid] = b2[tid];
    }
    if (tid < 128) {
        int r = tid;
        const float* lrow = loc + (size_t)(n0 + r) * 30;
        const float* vrow = vel + (size_t)(n0 + r) * 30;
        __half* drow = (__half*)(sm + EA_OFF + r * (PE * 2));
#pragma unroll
        for (int k = 0; k < 64; k++) {
            float v = 0.f;
            if (k < 60) {
                int f = k / 6, c6 = k % 6;
                v = (c6 < 3) ? lrow[f * 3 + c6] : vrow[f * 3 + c6 - 3];
            }
            drow[k] = __float2half(v);
        }
    }
    __syncthreads();

    gemm_zero(c);
    gemm_run(c, EA_OFF, PE * 2, wf1, 4);
    epi_relu_h(c, sm, EH_OFF, EB1_OFF);
    __syncthreads();

    gemm_zero(c);
    gemm_run(c, EH_OFF, PB * 2, wf2, 8);
    __syncthreads();
    epi_write_x_stage(c, sm, EB2_OFF, xout, n0, EH_OFF, true);
    __syncthreads();
    pre_from_stage(c, EH_OFF, nW1f, nb1, pd, ps, n0);
}

// ---------------------------------------------------------------------------
// loss
// ---------------------------------------------------------------------------
__global__ void loss_kernel(const float* __restrict__ hout, const float* __restrict__ loc,
                            const float* __restrict__ y, float* __restrict__ out) {
    int w = (blockIdx.x * blockDim.x + threadIdx.x) >> 5;
    int lane = threadIdx.x & 31;
    if (w >= BB) return;
    float ade = 0.f, fde = 0.f;
    for (int p = lane; p < 160; p += 32) {
        int node = w * 16 + p / NF;
        int f = p % NF;
        int base = node * 30 + f * 3;
        float dx = hout[base] + loc[base] - y[base];
        float dy = hout[base + 1] + loc[base + 1] - y[base + 1];
        float dz = hout[base + 2] + loc[base + 2] - y[base + 2];
        float d = sqrtf(dx * dx + dy * dy + dz * dz);
        ade += d;
        if (f == NF - 1) fde += d;
    }
#pragma unroll
    for (int o = 16; o; o >>= 1) {
        ade += __shfl_down_sync(0xffffffffu, ade, o);
        fde += __shfl_down_sync(0xffffffffu, fde, o);
    }
    if (lane == 0) {
        out[1 + w] = ade / 160.f;
        out[1 + BB + w] = fde / 16.f;
    }
}

__global__ void final_kernel(float* __restrict__ out) {
    __shared__ float s[256];
    float v = 0.f;
    for (int i = threadIdx.x; i < BB; i += 256) v += out[1 + i];
    s[threadIdx.x] = v;
    __syncthreads();
    for (int o = 128; o; o >>= 1) {
        if (threadIdx.x < o) s[threadIdx.x] += s[threadIdx.x + o];
        __syncthreads();
    }
    if (threadIdx.x == 0) out[0] = s[0] / (float)BB;
}

// ---------------------------------------------------------------------------
// host
// ---------------------------------------------------------------------------
extern "C" void kernel_launch(void* const* d_in, const int* in_sizes, int n_in,
                              void* d_out, int out_size) {
    int o = (n_in > 4 && in_sizes[4] == 1) ? 1 : 0;
    const float* loc = (const float*)d_in[0];
    const float* vel = (const float*)d_in[1];
    const float* y   = (const float*)d_in[2];
    const void*  eix = d_in[3];
    const float* embW1 = (const float*)d_in[4 + o];
    const float* embb1 = (const float*)d_in[5 + o];
    const float* embW2 = (const float*)d_in[6 + o];
    const float* embb2 = (const float*)d_in[7 + o];
    const float* msgW1 = (const float*)d_in[8 + o];
    const float* msgb1 = (const float*)d_in[9 + o];
    const float* msgW2 = (const float*)d_in[10 + o];
    const float* msgb2 = (const float*)d_in[11 + o];
    const float* updW1 = (const float*)d_in[12 + o];
    const float* updb1 = (const float*)d_in[13 + o];
    const float* updW2 = (const float*)d_in[14 + o];
    const float* updb2 = (const float*)d_in[15 + o];
    const float* hW1 = (const float*)d_in[16 + o];
    const float* hb1 = (const float*)d_in[17 + o];
    const float* hW2 = (const float*)d_in[18 + o];
    const float* hb2 = (const float*)d_in[19 + o];
    float* out = (float*)d_out;

    cudaFuncSetAttribute(upd_tc, cudaFuncAttributeMaxDynamicSharedMemorySize, DYNB_U);
    cudaFuncSetAttribute(embed_tc, cudaFuncAttributeMaxDynamicSharedMemorySize, DYNB_EM);

    __half *xhp, *xh2p, *pdp, *psp, *agghp;
    float *headp, *mfwp, *vbp;
    int *degip, *csrsp, *rowpp;
    uint4 *mW1f, *Mff, *uW1f, *uW2f, *eW1f, *eW2f, *hW1f, *hW2f;
    cudaGetSymbolAddress((void**)&xhp, g_xh);
    cudaGetSymbolAddress((void**)&xh2p, g_xh2);
    cudaGetSymbolAddress((void**)&pdp, g_pd);
    cudaGetSymbolAddress((void**)&psp, g_ps);
    cudaGetSymbolAddress((void**)&agghp, g_aggh);
    cudaGetSymbolAddress((void**)&degip, g_degi);
    cudaGetSymbolAddress((void**)&headp, g_head);
    cudaGetSymbolAddress((void**)&csrsp, g_csrs);
    cudaGetSymbolAddress((void**)&rowpp, g_rowp);
    cudaGetSymbolAddress((void**)&mfwp, g_mfw);
    cudaGetSymbolAddress((void**)&vbp, g_vb);
    cudaGetSymbolAddress((void**)&mW1f, g_mW1f);
    cudaGetSymbolAddress((void**)&Mff, g_Mff);
    cudaGetSymbolAddress((void**)&uW1f, g_uW1f);
    cudaGetSymbolAddress((void**)&uW2f, g_uW2f);
    cudaGetSymbolAddress((void**)&eW1f, g_eW1f);
    cudaGetSymbolAddress((void**)&eW2f, g_eW2f);
    cudaGetSymbolAddress((void**)&hW1f, g_hW1f);
    cudaGetSymbolAddress((void**)&hW2f, g_hW2f);

    detect_kernel<<<1, 32>>>((const int*)eix);
    cudaMemsetAsync(degip, 0, NN * sizeof(int));
    idx_kernel<<<EE / 256, 256>>>(eix);
    scanA_kernel<<<NN / 1024, 1024>>>();
    scanB_kernel<<<1, 32>>>();
    scanC_kernel<<<NN / 1024, 1024>>>();
    fill_kernel<<<EE / 256, 256>>>();
    mf_kernel<<<LL, 256>>>(msgW2, updW1, msgb2);
    prep_fragk<<<dim3(LL, 16), 256>>>(msgW1, (__half*)mW1f, 256, 128, 128, 256 * 128, 32768);
    prep_fragk<<<dim3(LL, 16), 256>>>(updW1, (__half*)uW1f, 256, 128, 128, 256 * 128, 32768);
    prep_fragk<<<dim3(LL, 8), 256>>>(updW2, (__half*)uW2f, 128, 128, 128, 128 * 128, 16384);
    prep_fragk<<<dim3(LL, 8), 256>>>(mfwp, (__half*)Mff, 128, 128, 128, 16384, 16384);
    prep_fragk<<<dim3(1, 4), 256>>>(embW1, (__half*)eW1f, 60, 128, 128, 0, 0);
    prep_fragk<<<dim3(1, 8), 256>>>(embW2, (__half*)eW2f, 128, 128, 128, 0, 0);
    prep_fragk<<<dim3(1, 8), 256>>>(hW1, (__half*)hW1f, 128, 128, 128, 0, 0);
    prep_fragk<<<dim3(1, 8), 256>>>(hW2, (__half*)hW2f, 128, 30, 30, 0, 0);

    embed_tc<<<NN / 128, 256, DYNB_EM>>>(loc, vel, eW1f, eW2f, embb1, embb2, xhp,
                                         mW1f, msgb1, pdp, psp);

    __half* xa = xhp;
    __half* xb = xh2p;
    for (int i = 0; i < LL; i++) {
        agg_csr<<<NN / 8, 256>>>(pdp, psp, csrsp, rowpp, agghp);
        int last = (i + 1 == LL);
        upd_tc<<<NN / 128, 256, DYNB_U>>>(
            xa, agghp,
            Mff + (size_t)i * 2048, vbp + (size_t)i * 128, degip,
            uW1f + (size_t)i * 4096, uW2f + (size_t)i * 2048,
            updb1 + (size_t)i * HH, updb2 + (size_t)i * HH, xb,
            last ? hW1f : mW1f + (size_t)(i + 1) * 4096,
            hW2f,
            last ? hb1 : msgb1 + (size_t)(i + 1) * HH,
            hb2,
            pdp, psp, headp, last ? 2 : 1);
        __half* t = xa; xa = xb; xb = t;
    }
    loss_kernel<<<(BB * 32 + 127) / 128, 128>>>(headp, loc, y, out);
    final_kernel<<<1, 256>>>(out);
}